// round 2
// baseline (speedup 1.0000x reference)
#include <cuda_runtime.h>

// ---------------- problem constants ----------------
#define T_TOK 50176     // 64*28*28 tokens
#define D_IN  512
#define D_HID 2048
#define N_EXP 3
#define R_LORA 8

// ---------------- device scratch (no cudaMalloc allowed) ----------------
__device__ float g_hidden[(size_t)T_TOK * D_HID];  // gelu(x@W1+b1), 411 MB
__device__ float g_act[(size_t)T_TOK * 2 * R_LORA]; // p_k * gelu(x @ w_down[e_k]), [T,16]

__device__ __forceinline__ float gelu_exact(float v) {
    return 0.5f * v * (1.0f + erff(v * 0.70710678118654752f));
}

// =====================================================================
// Kernel 1: LoRA down-proj + GELU + gate weight for the 2 top-k experts.
// One warp handles 8 tokens; all 3 experts' w_down (transposed) in smem.
// g_act[t*16 + k*8 + r] = topk_probs[t,k] * gelu( sum_d x[t,d]*w_down[e_k,d,r] )
// =====================================================================
__global__ __launch_bounds__(256) void lora_down_kernel(
    const float* __restrict__ x,
    const float* __restrict__ w_down,        // [E, D, R]
    const float* __restrict__ probs,         // [T, 2]
    const int* __restrict__ idx)             // [T, 2] int32
{
    __shared__ float wdT[N_EXP * R_LORA * D_IN];  // [e][r][d], 48 KB
    int tid = threadIdx.x;
    for (int i = tid; i < N_EXP * D_IN * R_LORA; i += 256) {
        int e   = i >> 12;          // / (512*8)
        int rem = i & 4095;
        int d   = rem >> 3;
        int r   = rem & 7;
        wdT[e * 4096 + r * 512 + d] = w_down[i];
    }
    __syncthreads();

    int warp = tid >> 5, lid = tid & 31;
    int tBase = blockIdx.x * 64 + warp * 8;

    for (int j = 0; j < 8; j++) {
        int t = tBase + j;
        int e0 = idx[2 * t];
        int e1 = idx[2 * t + 1];
        float p0 = probs[2 * t];
        float p1 = probs[2 * t + 1];
        const float* wd0 = &wdT[e0 * 4096];
        const float* wd1 = &wdT[e1 * 4096];
        const float* xr = x + (size_t)t * D_IN;

        float acc0[8] = {0,0,0,0,0,0,0,0};
        float acc1[8] = {0,0,0,0,0,0,0,0};
        #pragma unroll
        for (int i = 0; i < 16; i++) {
            float xv = xr[lid + 32 * i];
            #pragma unroll
            for (int r = 0; r < 8; r++) {
                acc0[r] = fmaf(xv, wd0[r * 512 + lid + 32 * i], acc0[r]);
                acc1[r] = fmaf(xv, wd1[r * 512 + lid + 32 * i], acc1[r]);
            }
        }
        #pragma unroll
        for (int r = 0; r < 8; r++) {
            #pragma unroll
            for (int off = 16; off; off >>= 1) {
                acc0[r] += __shfl_xor_sync(0xffffffffu, acc0[r], off);
                acc1[r] += __shfl_xor_sync(0xffffffffu, acc1[r], off);
            }
        }
        if (lid == 0) {
            float* a = &g_act[(size_t)t * 16];
            #pragma unroll
            for (int r = 0; r < 8; r++) {
                a[r]     = p0 * gelu_exact(acc0[r]);
                a[8 + r] = p1 * gelu_exact(acc1[r]);
            }
        }
    }
}

// =====================================================================
// Kernel 2: g_hidden = gelu(x @ W1 + b1).  128x128x8 tiled SGEMM.
// =====================================================================
__global__ __launch_bounds__(256) void gemm1_gelu_kernel(
    const float* __restrict__ A,     // x [T, 512]
    const float* __restrict__ B,     // W1 [512, 2048]
    const float* __restrict__ bias)  // b1 [2048]
{
    const int K = D_IN, N = D_HID;
    __shared__ float As[8][132];   // transposed A tile, padded
    __shared__ float Bs[8][128];

    int tid = threadIdx.x;
    int mBase = blockIdx.y * 128;
    int nBase = blockIdx.x * 128;
    int tr = tid >> 4, tc = tid & 15;   // 16x16 thread grid, 8x8 each

    float acc[8][8] = {};

    int a_row = tid >> 1, a_col = (tid & 1) * 4;
    int b_row = tid >> 5, b_col = (tid & 31) * 4;
    const float* Ag = A + (size_t)(mBase + a_row) * K + a_col;
    const float* Bg = B + (size_t)b_row * N + nBase + b_col;

    #pragma unroll 1
    for (int kt = 0; kt < K; kt += 8) {
        float4 av = *(const float4*)(Ag + kt);
        float4 bv = *(const float4*)(Bg + (size_t)kt * N);
        __syncthreads();
        As[a_col + 0][a_row] = av.x;
        As[a_col + 1][a_row] = av.y;
        As[a_col + 2][a_row] = av.z;
        As[a_col + 3][a_row] = av.w;
        *(float4*)&Bs[b_row][b_col] = bv;
        __syncthreads();
        #pragma unroll
        for (int k = 0; k < 8; k++) {
            float4 a0 = *(const float4*)&As[k][tr * 8];
            float4 a1 = *(const float4*)&As[k][tr * 8 + 4];
            float4 b0 = *(const float4*)&Bs[k][tc * 8];
            float4 b1 = *(const float4*)&Bs[k][tc * 8 + 4];
            float ar[8] = {a0.x, a0.y, a0.z, a0.w, a1.x, a1.y, a1.z, a1.w};
            float br[8] = {b0.x, b0.y, b0.z, b0.w, b1.x, b1.y, b1.z, b1.w};
            #pragma unroll
            for (int ii = 0; ii < 8; ii++)
                #pragma unroll
                for (int jj = 0; jj < 8; jj++)
                    acc[ii][jj] = fmaf(ar[ii], br[jj], acc[ii][jj]);
        }
    }

    // epilogue: + bias, gelu, store
    float bb[8];
    #pragma unroll
    for (int jj = 0; jj < 8; jj++) bb[jj] = bias[nBase + tc * 8 + jj];

    #pragma unroll
    for (int i = 0; i < 8; i++) {
        int row = mBase + tr * 8 + i;
        float* Crow = g_hidden + (size_t)row * N + nBase + tc * 8;
        float4 o0, o1;
        o0.x = gelu_exact(acc[i][0] + bb[0]);
        o0.y = gelu_exact(acc[i][1] + bb[1]);
        o0.z = gelu_exact(acc[i][2] + bb[2]);
        o0.w = gelu_exact(acc[i][3] + bb[3]);
        o1.x = gelu_exact(acc[i][4] + bb[4]);
        o1.y = gelu_exact(acc[i][5] + bb[5]);
        o1.z = gelu_exact(acc[i][6] + bb[6]);
        o1.w = gelu_exact(acc[i][7] + bb[7]);
        *(float4*)Crow = o0;
        *(float4*)(Crow + 4) = o1;
    }
}

// =====================================================================
// Kernel 3: out = g_hidden @ W2 + b2 + MoE-up (folded into epilogue).
// Per-tile w_up slice (3 experts x 8 ranks x 128 cols) lives in smem.
// =====================================================================
__global__ __launch_bounds__(256) void gemm2_moe_kernel(
    const float* __restrict__ B,     // W2 [2048, 512]
    const float* __restrict__ bias,  // b2 [512]
    const float* __restrict__ w_up,  // [E, R, D]
    const int* __restrict__ idx,     // [T, 2] int32
    float* __restrict__ out)         // [T, 512]
{
    const int K = D_HID, N = D_IN;
    __shared__ float As[8][132];
    __shared__ float Bs[8][128];
    __shared__ float wu_s[N_EXP * R_LORA * 128];  // [e][r][c], 12 KB

    int tid = threadIdx.x;
    int mBase = blockIdx.y * 128;
    int nBase = blockIdx.x * 128;
    int tr = tid >> 4, tc = tid & 15;

    // stage this block's w_up column slice
    for (int i = tid; i < N_EXP * R_LORA * 128; i += 256) {
        int e   = i >> 10;
        int rem = i & 1023;
        int r   = rem >> 7;
        int c   = rem & 127;
        wu_s[i] = w_up[e * (R_LORA * D_IN) + r * D_IN + nBase + c];
    }

    float acc[8][8] = {};

    int a_row = tid >> 1, a_col = (tid & 1) * 4;
    int b_row = tid >> 5, b_col = (tid & 31) * 4;
    const float* Ag = g_hidden + (size_t)(mBase + a_row) * K + a_col;
    const float* Bg = B + (size_t)b_row * N + nBase + b_col;

    #pragma unroll 1
    for (int kt = 0; kt < K; kt += 8) {
        float4 av = *(const float4*)(Ag + kt);
        float4 bv = *(const float4*)(Bg + (size_t)kt * N);
        __syncthreads();
        As[a_col + 0][a_row] = av.x;
        As[a_col + 1][a_row] = av.y;
        As[a_col + 2][a_row] = av.z;
        As[a_col + 3][a_row] = av.w;
        *(float4*)&Bs[b_row][b_col] = bv;
        __syncthreads();
        #pragma unroll
        for (int k = 0; k < 8; k++) {
            float4 a0 = *(const float4*)&As[k][tr * 8];
            float4 a1 = *(const float4*)&As[k][tr * 8 + 4];
            float4 b0 = *(const float4*)&Bs[k][tc * 8];
            float4 b1 = *(const float4*)&Bs[k][tc * 8 + 4];
            float ar[8] = {a0.x, a0.y, a0.z, a0.w, a1.x, a1.y, a1.z, a1.w};
            float br[8] = {b0.x, b0.y, b0.z, b0.w, b1.x, b1.y, b1.z, b1.w};
            #pragma unroll
            for (int ii = 0; ii < 8; ii++)
                #pragma unroll
                for (int jj = 0; jj < 8; jj++)
                    acc[ii][jj] = fmaf(ar[ii], br[jj], acc[ii][jj]);
        }
    }

    float bb[8];
    #pragma unroll
    for (int jj = 0; jj < 8; jj++) bb[jj] = bias[nBase + tc * 8 + jj];

    #pragma unroll
    for (int i = 0; i < 8; i++) {
        int t = mBase + tr * 8 + i;
        int e0 = idx[2 * t];
        int e1 = idx[2 * t + 1];
        const float* a = &g_act[(size_t)t * 16];
        float av0[8], av1[8];
        #pragma unroll
        for (int r = 0; r < 8; r++) { av0[r] = a[r]; av1[r] = a[8 + r]; }
        const float* u0 = &wu_s[e0 * 1024 + tc * 8];
        const float* u1 = &wu_s[e1 * 1024 + tc * 8];

        float o[8];
        #pragma unroll
        for (int cc = 0; cc < 8; cc++) {
            float s = acc[i][cc] + bb[cc];
            #pragma unroll
            for (int r = 0; r < 8; r++) {
                s = fmaf(av0[r], u0[r * 128 + cc], s);
                s = fmaf(av1[r], u1[r * 128 + cc], s);
            }
            o[cc] = s;
        }
        float* Crow = out + (size_t)t * N + nBase + tc * 8;
        *(float4*)(Crow)     = make_float4(o[0], o[1], o[2], o[3]);
        *(float4*)(Crow + 4) = make_float4(o[4], o[5], o[6], o[7]);
    }
}

// =====================================================================
// launch
// =====================================================================
extern "C" void kernel_launch(void* const* d_in, const int* in_sizes, int n_in,
                              void* d_out, int out_size) {
    const float* x          = (const float*)d_in[0];
    const float* W1         = (const float*)d_in[1];
    const float* b1         = (const float*)d_in[2];
    const float* W2         = (const float*)d_in[3];
    const float* b2         = (const float*)d_in[4];
    const float* w_down     = (const float*)d_in[5];
    const float* w_up       = (const float*)d_in[6];
    // d_in[7] = gate_probs (unused; top-k already materialized)
    const float* topk_probs = (const float*)d_in[8];
    const int*   topk_idx   = (const int*)d_in[9];   // int32 (JAX default, no x64)
    float* out = (float*)d_out;

    (void)in_sizes; (void)n_in; (void)out_size;

    lora_down_kernel<<<T_TOK / 64, 256>>>(x, w_down, topk_probs, topk_idx);

    dim3 g1(D_HID / 128, T_TOK / 128);
    gemm1_gelu_kernel<<<g1, 256>>>(x, W1, b1);

    dim3 g2(D_IN / 128, T_TOK / 128);
    gemm2_moe_kernel<<<g2, 256>>>(W2, b2, w_up, topk_idx, out);
}

// round 4
// speedup vs baseline: 1.9652x; 1.9652x over previous
#include <cuda_runtime.h>
#include <cuda_bf16.h>
#include <cstdint>

// ---------------- problem constants ----------------
#define T_TOK 50176     // 64*28*28 tokens
#define D_IN  512
#define D_HID 2048
#define K2    2112      // D_HID + 24 moe cols + 40 zero pad (multiple of 32)
#define N_EXP 3
#define R_LORA 8

// ---------------- device scratch (zero-initialized at module load) -------
__device__ __nv_bfloat16 g_xhi[(size_t)T_TOK * D_IN];
__device__ __nv_bfloat16 g_xlo[(size_t)T_TOK * D_IN];
__device__ __nv_bfloat16 g_w1t_hi[(size_t)D_HID * D_IN];   // W1^T [2048,512]
__device__ __nv_bfloat16 g_w1t_lo[(size_t)D_HID * D_IN];
__device__ __nv_bfloat16 g_w2e_hi[(size_t)D_IN * K2];      // [512,2112] = W2^T ++ w_up^T ++ 0
__device__ __nv_bfloat16 g_w2e_lo[(size_t)D_IN * K2];
__device__ __nv_bfloat16 g_hhi[(size_t)T_TOK * K2];        // hidden ++ a24 ++ 0-pad
__device__ __nv_bfloat16 g_hlo[(size_t)T_TOK * K2];

__device__ __forceinline__ float gelu_exact(float v) {
    return 0.5f * v * (1.0f + erff(v * 0.70710678118654752f));
}
__device__ __forceinline__ uint32_t smem_to_u32(const void* p) {
    uint32_t a;
    asm("{ .reg .u64 t; cvta.to.shared.u64 t, %1; cvt.u32.u64 %0, t; }" : "=r"(a) : "l"(p));
    return a;
}

// ---------------- base-ISA async copy / ldmatrix / mma helpers ----------
#define CP_ASYNC16(dst_smem, src_gmem) \
    asm volatile("cp.async.cg.shared.global [%0], [%1], 16;" \
        :: "r"(dst_smem), "l"(src_gmem) : "memory")
#define CP_COMMIT() asm volatile("cp.async.commit_group;" ::: "memory")
#define CP_WAIT1()  asm volatile("cp.async.wait_group 1;" ::: "memory")
#define CP_WAIT0()  asm volatile("cp.async.wait_group 0;" ::: "memory")

#define LDMATRIX_X4(r0, r1, r2, r3, addr) \
    asm volatile("ldmatrix.sync.aligned.m8n8.x4.shared.b16 {%0,%1,%2,%3}, [%4];" \
        : "=r"(r0), "=r"(r1), "=r"(r2), "=r"(r3) : "r"(addr))

#define MMA_BF16(c, a, b0_, b1_) \
    asm volatile("mma.sync.aligned.m16n8k16.row.col.f32.bf16.bf16.f32 " \
        "{%0,%1,%2,%3}, {%4,%5,%6,%7}, {%8,%9}, {%0,%1,%2,%3};" \
        : "+f"((c)[0]), "+f"((c)[1]), "+f"((c)[2]), "+f"((c)[3]) \
        : "r"((a)[0]), "r"((a)[1]), "r"((a)[2]), "r"((a)[3]), "r"(b0_), "r"(b1_))

// =====================================================================
// Prep: fp32 -> bf16 hi/lo split (elementwise, float4)
// =====================================================================
__global__ __launch_bounds__(256) void split_kernel(
    const float* __restrict__ in, __nv_bfloat16* __restrict__ hi,
    __nv_bfloat16* __restrict__ lo, int n4)
{
    int i = blockIdx.x * 256 + threadIdx.x;
    if (i >= n4) return;
    float4 v = ((const float4*)in)[i];
    __nv_bfloat16 h0 = __float2bfloat16(v.x), h1 = __float2bfloat16(v.y);
    __nv_bfloat16 h2 = __float2bfloat16(v.z), h3 = __float2bfloat16(v.w);
    __nv_bfloat16 l0 = __float2bfloat16(v.x - __bfloat162float(h0));
    __nv_bfloat16 l1 = __float2bfloat16(v.y - __bfloat162float(h1));
    __nv_bfloat16 l2 = __float2bfloat16(v.z - __bfloat162float(h2));
    __nv_bfloat16 l3 = __float2bfloat16(v.w - __bfloat162float(h3));
    ((__nv_bfloat162*)hi)[2*i]   = __halves2bfloat162(h0, h1);
    ((__nv_bfloat162*)hi)[2*i+1] = __halves2bfloat162(h2, h3);
    ((__nv_bfloat162*)lo)[2*i]   = __halves2bfloat162(l0, l1);
    ((__nv_bfloat162*)lo)[2*i+1] = __halves2bfloat162(l2, l3);
}

// =====================================================================
// Prep: transpose + split. w [rows, cols] -> t[c][r] (pitch opitch)
// =====================================================================
__global__ void transpose_split_kernel(
    const float* __restrict__ w, __nv_bfloat16* __restrict__ thi,
    __nv_bfloat16* __restrict__ tlo, int rows, int cols, int opitch)
{
    __shared__ float tile[32][33];
    int c0 = blockIdx.x * 32, r0 = blockIdx.y * 32;
    int tx = threadIdx.x, ty = threadIdx.y;
    #pragma unroll
    for (int i = 0; i < 4; i++)
        tile[ty + 8*i][tx] = w[(size_t)(r0 + ty + 8*i) * cols + c0 + tx];
    __syncthreads();
    #pragma unroll
    for (int i = 0; i < 4; i++) {
        float v = tile[tx][ty + 8*i];
        __nv_bfloat16 h = __float2bfloat16(v);
        __nv_bfloat16 l = __float2bfloat16(v - __bfloat162float(h));
        size_t o = (size_t)(c0 + ty + 8*i) * opitch + r0 + tx;
        thi[o] = h; tlo[o] = l;
    }
}

// =====================================================================
// Prep: fill w2ext cols [2048, 2112): w_up rows then zeros
// =====================================================================
__global__ __launch_bounds__(256) void w2ext_extra_kernel(const float* __restrict__ w_up)
{
    int i = blockIdx.x * 256 + threadIdx.x;   // over 512*64
    int n = i >> 6, c = i & 63;
    float v = 0.0f;
    if (c < N_EXP * R_LORA) v = w_up[(size_t)c * D_IN + n];  // [E,R,D] flat
    __nv_bfloat16 h = __float2bfloat16(v);
    __nv_bfloat16 l = __float2bfloat16(v - __bfloat162float(h));
    size_t o = (size_t)n * K2 + D_HID + c;
    g_w2e_hi[o] = h; g_w2e_lo[o] = l;
}

// =====================================================================
// LoRA down-proj + GELU + gate weight -> a24 block of g_h (hi/lo bf16)
// =====================================================================
__global__ __launch_bounds__(256) void lora_down_kernel(
    const float* __restrict__ x,
    const float* __restrict__ w_down,        // [E, D, R]
    const float* __restrict__ probs,         // [T, 2]
    const int* __restrict__ idx)             // [T, 2] int32
{
    __shared__ float wdT[N_EXP * R_LORA * D_IN];  // [e][r][d], 48 KB
    int tid = threadIdx.x;
    for (int i = tid; i < N_EXP * D_IN * R_LORA; i += 256) {
        int e = i >> 12, rem = i & 4095, d = rem >> 3, r = rem & 7;
        wdT[e * 4096 + r * 512 + d] = w_down[i];
    }
    __syncthreads();

    int warp = tid >> 5, lid = tid & 31;
    int tBase = blockIdx.x * 64 + warp * 8;

    for (int j = 0; j < 8; j++) {
        int t = tBase + j;
        int e0 = idx[2 * t], e1 = idx[2 * t + 1];
        float p0 = probs[2 * t], p1 = probs[2 * t + 1];
        const float* wd0 = &wdT[e0 * 4096];
        const float* wd1 = &wdT[e1 * 4096];
        const float* xr = x + (size_t)t * D_IN;

        float acc0[8] = {}, acc1[8] = {};
        #pragma unroll
        for (int i = 0; i < 16; i++) {
            float xv = xr[lid + 32 * i];
            #pragma unroll
            for (int r = 0; r < 8; r++) {
                acc0[r] = fmaf(xv, wd0[r * 512 + lid + 32 * i], acc0[r]);
                acc1[r] = fmaf(xv, wd1[r * 512 + lid + 32 * i], acc1[r]);
            }
        }
        #pragma unroll
        for (int r = 0; r < 8; r++) {
            #pragma unroll
            for (int off = 16; off; off >>= 1) {
                acc0[r] += __shfl_xor_sync(0xffffffffu, acc0[r], off);
                acc1[r] += __shfl_xor_sync(0xffffffffu, acc1[r], off);
            }
        }
        if (lid == 0) {
            float vals[N_EXP * R_LORA];
            #pragma unroll
            for (int s = 0; s < N_EXP * R_LORA; s++) vals[s] = 0.0f;
            #pragma unroll
            for (int r = 0; r < 8; r++) {
                vals[e0 * 8 + r] += p0 * gelu_exact(acc0[r]);
                vals[e1 * 8 + r] += p1 * gelu_exact(acc1[r]);
            }
            size_t base = (size_t)t * K2 + D_HID;
            #pragma unroll
            for (int s = 0; s < N_EXP * R_LORA; s++) {
                __nv_bfloat16 h = __float2bfloat16(vals[s]);
                __nv_bfloat16 l = __float2bfloat16(vals[s] - __bfloat162float(h));
                g_hhi[base + s] = h; g_hlo[base + s] = l;
            }
        }
    }
}

// =====================================================================
// bf16-split GEMM via mma.sync (HMMA tensor cores, base-ISA PTX).
// CTA tile 128x128, 8 warps (warp tile 64x32), Kstage=32, cp.async
// double-buffered. C = Ahi*Bhi + Ahi*Blo + Alo*Bhi, fp32 accum.
// smem per stage: 4 matrices [128 rows][40 bf16] (pad for conflict-free
// ldmatrix), 10240 B each => 40960 B/stage, 2 stages, + bias slice.
// =====================================================================
#define MAT_BYTES 10240     // 128 * 40 * 2
#define STAGE_BYTES 40960
#define GSMEM_BYTES (2 * STAGE_BYTES + 512)

template<int KTOT, int LDA, int LDB, bool IS_GEMM1>
__global__ __launch_bounds__(256, 1) void mma_gemm_kernel(
    const __nv_bfloat16* __restrict__ Ahi, const __nv_bfloat16* __restrict__ Alo,
    const __nv_bfloat16* __restrict__ Bhi, const __nv_bfloat16* __restrict__ Blo,
    const float* __restrict__ bias,
    __nv_bfloat16* __restrict__ OutHi, __nv_bfloat16* __restrict__ OutLo,
    float* __restrict__ OutF)
{
    extern __shared__ char sm[];
    uint32_t sb = smem_to_u32(sm);
    float* bias_s = (float*)(sm + 2 * STAGE_BYTES);

    int tid = threadIdx.x, lane = tid & 31, wid = tid >> 5;
    int wm = wid >> 2, wn = wid & 3;          // warp grid 2 x 4
    int nBase = blockIdx.x * 128, mBase = blockIdx.y * 128;

    if (tid < 128) bias_s[tid] = bias[nBase + tid];

    // loader mapping: each thread: row = tid>>1, chunks {c0, c0+1} (16B each)
    int lrow = tid >> 1;
    int lcc  = (tid & 1) * 2;

    const __nv_bfloat16* gA = (const __nv_bfloat16*)0;
    // global row pointers (element offsets)
    size_t gArow = (size_t)(mBase + lrow) * LDA;
    size_t gBrow = (size_t)(nBase + lrow) * LDB;
    uint32_t srowoff = (uint32_t)lrow * 80;   // bytes within a matrix

    const int NS = KTOT / 32;

    // accumulators
    float acc[4][4][4];
    #pragma unroll
    for (int i = 0; i < 4; i++)
        #pragma unroll
        for (int j = 0; j < 4; j++)
            #pragma unroll
            for (int q = 0; q < 4; q++) acc[i][j][q] = 0.0f;

    // ---- prologue: stage 0 ----
    {
        uint32_t s0 = sb;
        #pragma unroll
        for (int c = 0; c < 2; ++c) {
            uint32_t so = srowoff + (uint32_t)(lcc + c) * 16;
            int ge = (lcc + c) * 8;           // element offset in k
            CP_ASYNC16(s0 +               so, Ahi + gArow + ge);
            CP_ASYNC16(s0 +   MAT_BYTES + so, Alo + gArow + ge);
            CP_ASYNC16(s0 + 2*MAT_BYTES + so, Bhi + gBrow + ge);
            CP_ASYNC16(s0 + 3*MAT_BYTES + so, Blo + gBrow + ge);
        }
        CP_COMMIT();
    }

    // fragment address components (constant across stages)
    uint32_t a_off = (uint32_t)(wm * 64 + (lane & 15)) * 80 + (uint32_t)((lane >> 4) * 8) * 2;
    uint32_t b_off = (uint32_t)(wn * 32 + (lane & 7) + ((lane >> 4) << 3)) * 80
                   + (uint32_t)(((lane >> 3) & 1) * 8) * 2;

    #pragma unroll 1
    for (int s = 0; s < NS; ++s) {
        if (s + 1 < NS) {
            uint32_t sbuf = sb + ((s + 1) & 1) * STAGE_BYTES;
            int kt = (s + 1) * 32;
            #pragma unroll
            for (int c = 0; c < 2; ++c) {
                uint32_t so = srowoff + (uint32_t)(lcc + c) * 16;
                int ge = kt + (lcc + c) * 8;
                CP_ASYNC16(sbuf +               so, Ahi + gArow + ge);
                CP_ASYNC16(sbuf +   MAT_BYTES + so, Alo + gArow + ge);
                CP_ASYNC16(sbuf + 2*MAT_BYTES + so, Bhi + gBrow + ge);
                CP_ASYNC16(sbuf + 3*MAT_BYTES + so, Blo + gBrow + ge);
            }
            CP_COMMIT();
            CP_WAIT1();
        } else {
            CP_WAIT0();
        }
        __syncthreads();

        uint32_t buf = sb + (s & 1) * STAGE_BYTES;
        #pragma unroll
        for (int ks = 0; ks < 2; ++ks) {
            uint32_t kb = (uint32_t)(ks * 16) * 2;
            // A fragments (hi, lo), 4 m-tiles
            uint32_t ah[4][4], al[4][4];
            #pragma unroll
            for (int i = 0; i < 4; ++i) {
                uint32_t ad = buf + a_off + (uint32_t)(i * 16) * 80 + kb;
                LDMATRIX_X4(ah[i][0], ah[i][1], ah[i][2], ah[i][3], ad);
                LDMATRIX_X4(al[i][0], al[i][1], al[i][2], al[i][3], ad + MAT_BYTES);
            }
            // B fragments (hi, lo), 4 n-tiles (two x4 loads each comp)
            uint32_t bh[4][2], bl[4][2];
            #pragma unroll
            for (int jj = 0; jj < 2; ++jj) {
                uint32_t bd = buf + 2*MAT_BYTES + b_off + (uint32_t)(jj * 16) * 80 + kb;
                LDMATRIX_X4(bh[2*jj][0], bh[2*jj][1], bh[2*jj+1][0], bh[2*jj+1][1], bd);
                LDMATRIX_X4(bl[2*jj][0], bl[2*jj][1], bl[2*jj+1][0], bl[2*jj+1][1], bd + MAT_BYTES);
            }
            // 3-term split MMAs
            #pragma unroll
            for (int i = 0; i < 4; ++i)
                #pragma unroll
                for (int j = 0; j < 4; ++j) {
                    MMA_BF16(acc[i][j], ah[i], bh[j][0], bh[j][1]);
                    MMA_BF16(acc[i][j], ah[i], bl[j][0], bl[j][1]);
                    MMA_BF16(acc[i][j], al[i], bh[j][0], bh[j][1]);
                }
        }
        __syncthreads();
    }

    // ---- epilogue ----
    int g = lane >> 2, tq = lane & 3;
    #pragma unroll
    for (int i = 0; i < 4; ++i) {
        int row0 = mBase + wm * 64 + i * 16 + g;
        int row1 = row0 + 8;
        #pragma unroll
        for (int j = 0; j < 4; ++j) {
            int nloc = wn * 32 + j * 8 + tq * 2;
            float b0 = bias_s[nloc], b1 = bias_s[nloc + 1];
            float v0 = acc[i][j][0] + b0, v1 = acc[i][j][1] + b1;
            float v2 = acc[i][j][2] + b0, v3 = acc[i][j][3] + b1;
            if (IS_GEMM1) {
                v0 = gelu_exact(v0); v1 = gelu_exact(v1);
                v2 = gelu_exact(v2); v3 = gelu_exact(v3);
                __nv_bfloat16 h0 = __float2bfloat16(v0), h1 = __float2bfloat16(v1);
                __nv_bfloat16 h2 = __float2bfloat16(v2), h3 = __float2bfloat16(v3);
                __nv_bfloat16 l0 = __float2bfloat16(v0 - __bfloat162float(h0));
                __nv_bfloat16 l1 = __float2bfloat16(v1 - __bfloat162float(h1));
                __nv_bfloat16 l2 = __float2bfloat16(v2 - __bfloat162float(h2));
                __nv_bfloat16 l3 = __float2bfloat16(v3 - __bfloat162float(h3));
                size_t o0 = (size_t)row0 * K2 + nBase + nloc;
                size_t o1 = (size_t)row1 * K2 + nBase + nloc;
                *(__nv_bfloat162*)(OutHi + o0) = __halves2bfloat162(h0, h1);
                *(__nv_bfloat162*)(OutLo + o0) = __halves2bfloat162(l0, l1);
                *(__nv_bfloat162*)(OutHi + o1) = __halves2bfloat162(h2, h3);
                *(__nv_bfloat162*)(OutLo + o1) = __halves2bfloat162(l2, l3);
            } else {
                size_t o0 = (size_t)row0 * D_IN + nBase + nloc;
                size_t o1 = (size_t)row1 * D_IN + nBase + nloc;
                *(float2*)(OutF + o0) = make_float2(v0, v1);
                *(float2*)(OutF + o1) = make_float2(v2, v3);
            }
        }
    }
}

// =====================================================================
// launch
// =====================================================================
extern "C" void kernel_launch(void* const* d_in, const int* in_sizes, int n_in,
                              void* d_out, int out_size) {
    const float* x          = (const float*)d_in[0];
    const float* W1         = (const float*)d_in[1];
    const float* b1         = (const float*)d_in[2];
    const float* W2         = (const float*)d_in[3];
    const float* b2         = (const float*)d_in[4];
    const float* w_down     = (const float*)d_in[5];
    const float* w_up       = (const float*)d_in[6];
    const float* topk_probs = (const float*)d_in[8];
    const int*   topk_idx   = (const int*)d_in[9];
    float* out = (float*)d_out;
    (void)in_sizes; (void)n_in; (void)out_size;

    __nv_bfloat16 *xhi, *xlo, *w1h, *w1l, *w2h, *w2l, *hhi, *hlo;
    cudaGetSymbolAddress((void**)&xhi, g_xhi);
    cudaGetSymbolAddress((void**)&xlo, g_xlo);
    cudaGetSymbolAddress((void**)&w1h, g_w1t_hi);
    cudaGetSymbolAddress((void**)&w1l, g_w1t_lo);
    cudaGetSymbolAddress((void**)&w2h, g_w2e_hi);
    cudaGetSymbolAddress((void**)&w2l, g_w2e_lo);
    cudaGetSymbolAddress((void**)&hhi, g_hhi);
    cudaGetSymbolAddress((void**)&hlo, g_hlo);

    cudaFuncSetAttribute(mma_gemm_kernel<D_IN, D_IN, D_IN, true>,
                         cudaFuncAttributeMaxDynamicSharedMemorySize, GSMEM_BYTES);
    cudaFuncSetAttribute(mma_gemm_kernel<K2, K2, K2, false>,
                         cudaFuncAttributeMaxDynamicSharedMemorySize, GSMEM_BYTES);

    // prep
    int n4 = T_TOK * D_IN / 4;
    split_kernel<<<n4 / 256, 256>>>(x, xhi, xlo, n4);
    transpose_split_kernel<<<dim3(D_HID / 32, D_IN / 32), dim3(32, 8)>>>(W1, w1h, w1l, D_IN, D_HID, D_IN);
    transpose_split_kernel<<<dim3(D_IN / 32, D_HID / 32), dim3(32, 8)>>>(W2, w2h, w2l, D_HID, D_IN, K2);
    w2ext_extra_kernel<<<(D_IN * 64) / 256, 256>>>(w_up);

    // lora a24 block
    lora_down_kernel<<<T_TOK / 64, 256>>>(x, w_down, topk_probs, topk_idx);

    // GEMM1: hidden = gelu(x @ W1 + b1) -> g_h hi/lo (cols 0..2048)
    mma_gemm_kernel<D_IN, D_IN, D_IN, true>
        <<<dim3(D_HID / 128, T_TOK / 128), 256, GSMEM_BYTES>>>(
            xhi, xlo, w1h, w1l, b1, hhi, hlo, nullptr);

    // GEMM2: out = [hidden|a24] @ [W2;w_up] + b2
    mma_gemm_kernel<K2, K2, K2, false>
        <<<dim3(D_IN / 128, T_TOK / 128), 256, GSMEM_BYTES>>>(
            hhi, hlo, w2h, w2l, b2, nullptr, nullptr, out);
}

// round 5
// speedup vs baseline: 4.9306x; 2.5090x over previous
#include <cuda_runtime.h>
#include <cuda_fp16.h>
#include <cstdint>

// ---------------- problem constants ----------------
#define T_TOK 50176     // 64*28*28 tokens
#define D_IN  512
#define D_HID 2048
#define K2    2080      // D_HID + 24 moe cols + 8 zero pad (multiple of 32)
#define N_EXP 3
#define R_LORA 8

// ---------------- device scratch (zero-initialized at module load) -------
__device__ __half g_xh[(size_t)T_TOK * D_IN];        // x in fp16
__device__ __half g_w1t[(size_t)D_HID * D_IN];       // W1^T [2048,512]
__device__ __half g_w2e[(size_t)D_IN * K2];          // [512,2080] = W2^T ++ w_up^T ++ 0
__device__ __half g_h[(size_t)T_TOK * K2];           // hidden ++ a24 ++ 0-pad (pad never written)

__device__ __forceinline__ float gelu_exact(float v) {
    return 0.5f * v * (1.0f + erff(v * 0.70710678118654752f));
}
__device__ __forceinline__ uint32_t smem_to_u32(const void* p) {
    uint32_t a;
    asm("{ .reg .u64 t; cvta.to.shared.u64 t, %1; cvt.u32.u64 %0, t; }" : "=r"(a) : "l"(p));
    return a;
}

// ---------------- base-ISA async copy / ldmatrix / mma helpers ----------
#define CP_ASYNC16(dst_smem, src_gmem) \
    asm volatile("cp.async.cg.shared.global [%0], [%1], 16;" \
        :: "r"(dst_smem), "l"(src_gmem) : "memory")
#define CP_COMMIT() asm volatile("cp.async.commit_group;" ::: "memory")
#define CP_WAIT2()  asm volatile("cp.async.wait_group 2;" ::: "memory")

#define LDMATRIX_X4(r0, r1, r2, r3, addr) \
    asm volatile("ldmatrix.sync.aligned.m8n8.x4.shared.b16 {%0,%1,%2,%3}, [%4];" \
        : "=r"(r0), "=r"(r1), "=r"(r2), "=r"(r3) : "r"(addr))

#define MMA_FP16(c, a, b0_, b1_) \
    asm volatile("mma.sync.aligned.m16n8k16.row.col.f32.f16.f16.f32 " \
        "{%0,%1,%2,%3}, {%4,%5,%6,%7}, {%8,%9}, {%0,%1,%2,%3};" \
        : "+f"((c)[0]), "+f"((c)[1]), "+f"((c)[2]), "+f"((c)[3]) \
        : "r"((a)[0]), "r"((a)[1]), "r"((a)[2]), "r"((a)[3]), "r"(b0_), "r"(b1_))

// =====================================================================
// Prep: fp32 -> fp16 convert (elementwise, float4 -> half4)
// =====================================================================
__global__ __launch_bounds__(256) void cvt_kernel(
    const float* __restrict__ in, __half* __restrict__ out, int n4)
{
    int i = blockIdx.x * 256 + threadIdx.x;
    if (i >= n4) return;
    float4 v = ((const float4*)in)[i];
    __half2 h0 = __floats2half2_rn(v.x, v.y);
    __half2 h1 = __floats2half2_rn(v.z, v.w);
    ((__half2*)out)[2*i]   = h0;
    ((__half2*)out)[2*i+1] = h1;
}

// =====================================================================
// Prep: transpose + convert. w [rows, cols] -> t[c][r] (pitch opitch)
// =====================================================================
__global__ void transpose_cvt_kernel(
    const float* __restrict__ w, __half* __restrict__ t,
    int rows, int cols, int opitch)
{
    __shared__ float tile[32][33];
    int c0 = blockIdx.x * 32, r0 = blockIdx.y * 32;
    int tx = threadIdx.x, ty = threadIdx.y;
    #pragma unroll
    for (int i = 0; i < 4; i++)
        tile[ty + 8*i][tx] = w[(size_t)(r0 + ty + 8*i) * cols + c0 + tx];
    __syncthreads();
    #pragma unroll
    for (int i = 0; i < 4; i++) {
        float v = tile[tx][ty + 8*i];
        t[(size_t)(c0 + ty + 8*i) * opitch + r0 + tx] = __float2half_rn(v);
    }
}

// =====================================================================
// Prep: fill w2ext cols [2048, 2080): w_up rows then zeros
// =====================================================================
__global__ __launch_bounds__(256) void w2ext_extra_kernel(const float* __restrict__ w_up)
{
    int i = blockIdx.x * 256 + threadIdx.x;   // over 512*32
    int n = i >> 5, c = i & 31;
    float v = 0.0f;
    if (c < N_EXP * R_LORA) v = w_up[(size_t)c * D_IN + n];  // [E,R,D] flat
    g_w2e[(size_t)n * K2 + D_HID + c] = __float2half_rn(v);
}

// =====================================================================
// LoRA down-proj + GELU + gate weight -> a24 block of g_h (fp16)
// =====================================================================
__global__ __launch_bounds__(256) void lora_down_kernel(
    const float* __restrict__ x,
    const float* __restrict__ w_down,        // [E, D, R]
    const float* __restrict__ probs,         // [T, 2]
    const int* __restrict__ idx)             // [T, 2] int32
{
    __shared__ float wdT[N_EXP * R_LORA * D_IN];  // [e][r][d], 48 KB
    int tid = threadIdx.x;
    for (int i = tid; i < N_EXP * D_IN * R_LORA; i += 256) {
        int e = i >> 12, rem = i & 4095, d = rem >> 3, r = rem & 7;
        wdT[e * 4096 + r * 512 + d] = w_down[i];
    }
    __syncthreads();

    int warp = tid >> 5, lid = tid & 31;
    int tBase = blockIdx.x * 64 + warp * 8;

    for (int j = 0; j < 8; j++) {
        int t = tBase + j;
        int e0 = idx[2 * t], e1 = idx[2 * t + 1];
        float p0 = probs[2 * t], p1 = probs[2 * t + 1];
        const float* wd0 = &wdT[e0 * 4096];
        const float* wd1 = &wdT[e1 * 4096];
        const float* xr = x + (size_t)t * D_IN;

        float acc0[8] = {}, acc1[8] = {};
        #pragma unroll
        for (int i = 0; i < 16; i++) {
            float xv = xr[lid + 32 * i];
            #pragma unroll
            for (int r = 0; r < 8; r++) {
                acc0[r] = fmaf(xv, wd0[r * 512 + lid + 32 * i], acc0[r]);
                acc1[r] = fmaf(xv, wd1[r * 512 + lid + 32 * i], acc1[r]);
            }
        }
        #pragma unroll
        for (int r = 0; r < 8; r++) {
            #pragma unroll
            for (int off = 16; off; off >>= 1) {
                acc0[r] += __shfl_xor_sync(0xffffffffu, acc0[r], off);
                acc1[r] += __shfl_xor_sync(0xffffffffu, acc1[r], off);
            }
        }
        if (lid == 0) {
            float vals[N_EXP * R_LORA];
            #pragma unroll
            for (int s = 0; s < N_EXP * R_LORA; s++) vals[s] = 0.0f;
            #pragma unroll
            for (int r = 0; r < 8; r++) {
                vals[e0 * 8 + r] += p0 * gelu_exact(acc0[r]);
                vals[e1 * 8 + r] += p1 * gelu_exact(acc1[r]);
            }
            size_t base = (size_t)t * K2 + D_HID;
            #pragma unroll
            for (int s = 0; s < N_EXP * R_LORA; s++)
                g_h[base + s] = __float2half_rn(vals[s]);
        }
    }
}

// =====================================================================
// fp16 single-term GEMM via mma.sync (HMMA).  CTA tile 128x128, 8 warps
// (warp tile 64x32), Kstage=32, 4-buffer / depth-3 cp.async pipeline.
// smem per stage: A,B [128 rows][40 halfs] padded => 10240 B each.
// =====================================================================
#define MAT_BYTES 10240     // 128 * 40 * 2
#define STAGE_BYTES 20480
#define GSMEM_BYTES (4 * STAGE_BYTES + 512)

template<int KTOT, int LDA, int LDB, bool IS_GEMM1>
__global__ __launch_bounds__(256, 2) void mma_gemm_kernel(
    const __half* __restrict__ A, const __half* __restrict__ B,
    const float* __restrict__ bias,
    __half* __restrict__ OutH, float* __restrict__ OutF)
{
    extern __shared__ char sm[];
    uint32_t sb = smem_to_u32(sm);
    float* bias_s = (float*)(sm + 4 * STAGE_BYTES);

    int tid = threadIdx.x, lane = tid & 31, wid = tid >> 5;
    int wm = wid >> 2, wn = wid & 3;          // warp grid 2 x 4
    int nBase = blockIdx.x * 128, mBase = blockIdx.y * 128;

    if (tid < 128) bias_s[tid] = bias[nBase + tid];

    // loader: each thread fills 2 chunks (16B) of A and of B per stage
    int lrow = tid >> 1;
    int lcc  = (tid & 1) * 2;
    size_t gArow = (size_t)(mBase + lrow) * LDA;
    size_t gBrow = (size_t)(nBase + lrow) * LDB;
    uint32_t srowoff = (uint32_t)lrow * 80;

    const int NS = KTOT / 32;

    float acc[4][4][4];
    #pragma unroll
    for (int i = 0; i < 4; i++)
        #pragma unroll
        for (int j = 0; j < 4; j++)
            #pragma unroll
            for (int q = 0; q < 4; q++) acc[i][j][q] = 0.0f;

    // ---- prologue: stages 0..2 ----
    #pragma unroll
    for (int p = 0; p < 3; ++p) {
        if (p < NS) {
            uint32_t sbuf = sb + (uint32_t)p * STAGE_BYTES;
            int kt = p * 32;
            #pragma unroll
            for (int c = 0; c < 2; ++c) {
                uint32_t so = srowoff + (uint32_t)(lcc + c) * 16;
                int ge = kt + (lcc + c) * 8;
                CP_ASYNC16(sbuf +             so, A + gArow + ge);
                CP_ASYNC16(sbuf + MAT_BYTES + so, B + gBrow + ge);
            }
        }
        CP_COMMIT();
    }

    uint32_t a_off = (uint32_t)(wm * 64 + (lane & 15)) * 80 + (uint32_t)((lane >> 4) * 8) * 2;
    uint32_t b_off = (uint32_t)(wn * 32 + (lane & 7) + ((lane >> 4) << 3)) * 80
                   + (uint32_t)(((lane >> 3) & 1) * 8) * 2;

    #pragma unroll 1
    for (int s = 0; s < NS; ++s) {
        CP_WAIT2();
        __syncthreads();

        // issue next stage load (buffer (s+3)&3 == (s-1)&3, readers done)
        if (s + 3 < NS) {
            uint32_t sbuf = sb + (uint32_t)((s + 3) & 3) * STAGE_BYTES;
            int kt = (s + 3) * 32;
            #pragma unroll
            for (int c = 0; c < 2; ++c) {
                uint32_t so = srowoff + (uint32_t)(lcc + c) * 16;
                int ge = kt + (lcc + c) * 8;
                CP_ASYNC16(sbuf +             so, A + gArow + ge);
                CP_ASYNC16(sbuf + MAT_BYTES + so, B + gBrow + ge);
            }
        }
        CP_COMMIT();

        uint32_t buf = sb + (uint32_t)(s & 3) * STAGE_BYTES;
        #pragma unroll
        for (int ks = 0; ks < 2; ++ks) {
            uint32_t kb = (uint32_t)(ks * 16) * 2;
            uint32_t ah[4][4];
            #pragma unroll
            for (int i = 0; i < 4; ++i) {
                uint32_t ad = buf + a_off + (uint32_t)(i * 16) * 80 + kb;
                LDMATRIX_X4(ah[i][0], ah[i][1], ah[i][2], ah[i][3], ad);
            }
            uint32_t bh[4][2];
            #pragma unroll
            for (int jj = 0; jj < 2; ++jj) {
                uint32_t bd = buf + MAT_BYTES + b_off + (uint32_t)(jj * 16) * 80 + kb;
                LDMATRIX_X4(bh[2*jj][0], bh[2*jj][1], bh[2*jj+1][0], bh[2*jj+1][1], bd);
            }
            #pragma unroll
            for (int i = 0; i < 4; ++i)
                #pragma unroll
                for (int j = 0; j < 4; ++j)
                    MMA_FP16(acc[i][j], ah[i], bh[j][0], bh[j][1]);
        }
    }

    // ---- epilogue ----
    int g = lane >> 2, tq = lane & 3;
    #pragma unroll
    for (int i = 0; i < 4; ++i) {
        int row0 = mBase + wm * 64 + i * 16 + g;
        int row1 = row0 + 8;
        #pragma unroll
        for (int j = 0; j < 4; ++j) {
            int nloc = wn * 32 + j * 8 + tq * 2;
            float b0 = bias_s[nloc], b1 = bias_s[nloc + 1];
            float v0 = acc[i][j][0] + b0, v1 = acc[i][j][1] + b1;
            float v2 = acc[i][j][2] + b0, v3 = acc[i][j][3] + b1;
            if (IS_GEMM1) {
                v0 = gelu_exact(v0); v1 = gelu_exact(v1);
                v2 = gelu_exact(v2); v3 = gelu_exact(v3);
                size_t o0 = (size_t)row0 * K2 + nBase + nloc;
                size_t o1 = (size_t)row1 * K2 + nBase + nloc;
                *(__half2*)(OutH + o0) = __floats2half2_rn(v0, v1);
                *(__half2*)(OutH + o1) = __floats2half2_rn(v2, v3);
            } else {
                size_t o0 = (size_t)row0 * D_IN + nBase + nloc;
                size_t o1 = (size_t)row1 * D_IN + nBase + nloc;
                *(float2*)(OutF + o0) = make_float2(v0, v1);
                *(float2*)(OutF + o1) = make_float2(v2, v3);
            }
        }
    }
}

// =====================================================================
// launch
// =====================================================================
extern "C" void kernel_launch(void* const* d_in, const int* in_sizes, int n_in,
                              void* d_out, int out_size) {
    const float* x          = (const float*)d_in[0];
    const float* W1         = (const float*)d_in[1];
    const float* b1         = (const float*)d_in[2];
    const float* W2         = (const float*)d_in[3];
    const float* b2         = (const float*)d_in[4];
    const float* w_down     = (const float*)d_in[5];
    const float* w_up       = (const float*)d_in[6];
    const float* topk_probs = (const float*)d_in[8];
    const int*   topk_idx   = (const int*)d_in[9];
    float* out = (float*)d_out;
    (void)in_sizes; (void)n_in; (void)out_size;

    __half *xh, *w1t, *w2e, *hh;
    cudaGetSymbolAddress((void**)&xh,  g_xh);
    cudaGetSymbolAddress((void**)&w1t, g_w1t);
    cudaGetSymbolAddress((void**)&w2e, g_w2e);
    cudaGetSymbolAddress((void**)&hh,  g_h);

    cudaFuncSetAttribute(mma_gemm_kernel<D_IN, D_IN, D_IN, true>,
                         cudaFuncAttributeMaxDynamicSharedMemorySize, GSMEM_BYTES);
    cudaFuncSetAttribute(mma_gemm_kernel<K2, K2, K2, false>,
                         cudaFuncAttributeMaxDynamicSharedMemorySize, GSMEM_BYTES);

    // prep
    int n4 = T_TOK * D_IN / 4;
    cvt_kernel<<<n4 / 256, 256>>>(x, xh, n4);
    transpose_cvt_kernel<<<dim3(D_HID / 32, D_IN / 32), dim3(32, 8)>>>(W1, w1t, D_IN, D_HID, D_IN);
    transpose_cvt_kernel<<<dim3(D_IN / 32, D_HID / 32), dim3(32, 8)>>>(W2, w2e, D_HID, D_IN, K2);
    w2ext_extra_kernel<<<(D_IN * 32) / 256, 256>>>(w_up);

    // lora a24 block
    lora_down_kernel<<<T_TOK / 64, 256>>>(x, w_down, topk_probs, topk_idx);

    // GEMM1: hidden = gelu(x @ W1 + b1) -> g_h (cols 0..2048)
    mma_gemm_kernel<D_IN, D_IN, D_IN, true>
        <<<dim3(D_HID / 128, T_TOK / 128), 256, GSMEM_BYTES>>>(
            xh, w1t, b1, hh, nullptr);

    // GEMM2: out = [hidden|a24] @ [W2;w_up] + b2
    mma_gemm_kernel<K2, K2, K2, false>
        <<<dim3(D_IN / 128, T_TOK / 128), 256, GSMEM_BYTES>>>(
            hh, w2e, b2, nullptr, out);
}

// round 6
// speedup vs baseline: 4.9804x; 1.0101x over previous
#include <cuda_runtime.h>
#include <cuda_fp16.h>
#include <cstdint>

// ---------------- problem constants ----------------
#define T_TOK 50176     // 64*28*28 tokens
#define D_IN  512
#define D_HID 2048
#define K2    2080      // D_HID + 24 moe cols + 8 zero pad
#define N_EXP 3
#define R_LORA 8

// ---------------- device scratch (zero-initialized at module load) -------
__device__ __half g_xh[(size_t)T_TOK * D_IN];        // x in fp16
__device__ __half g_w1t[(size_t)D_HID * D_IN];       // W1^T [2048,512]
__device__ __half g_w2e[(size_t)D_IN * K2];          // [512,2080] = W2^T ++ w_up^T ++ 0
__device__ __half g_wdt[(size_t)32 * D_IN];          // w_down^T padded [32,512]
__device__ __half g_h[(size_t)T_TOK * K2];           // hidden ++ a24 ++ 0-pad

__device__ __forceinline__ float gelu_exact(float v) {
    return 0.5f * v * (1.0f + erff(v * 0.70710678118654752f));
}
__device__ __forceinline__ uint32_t smem_to_u32(const void* p) {
    uint32_t a;
    asm("{ .reg .u64 t; cvta.to.shared.u64 t, %1; cvt.u32.u64 %0, t; }" : "=r"(a) : "l"(p));
    return a;
}

// ---------------- base-ISA async copy / ldmatrix / mma helpers ----------
#define CP_ASYNC16(dst_smem, src_gmem) \
    asm volatile("cp.async.cg.shared.global [%0], [%1], 16;" \
        :: "r"(dst_smem), "l"(src_gmem) : "memory")
#define CP_COMMIT() asm volatile("cp.async.commit_group;" ::: "memory")
#define CP_WAIT1()  asm volatile("cp.async.wait_group 1;" ::: "memory")

#define LDMATRIX_X4(r0, r1, r2, r3, addr) \
    asm volatile("ldmatrix.sync.aligned.m8n8.x4.shared.b16 {%0,%1,%2,%3}, [%4];" \
        : "=r"(r0), "=r"(r1), "=r"(r2), "=r"(r3) : "r"(addr))

#define MMA_FP16(c, a, b0_, b1_) \
    asm volatile("mma.sync.aligned.m16n8k16.row.col.f32.f16.f16.f32 " \
        "{%0,%1,%2,%3}, {%4,%5,%6,%7}, {%8,%9}, {%0,%1,%2,%3};" \
        : "+f"((c)[0]), "+f"((c)[1]), "+f"((c)[2]), "+f"((c)[3]) \
        : "r"((a)[0]), "r"((a)[1]), "r"((a)[2]), "r"((a)[3]), "r"(b0_), "r"(b1_))

// =====================================================================
// Prep: fp32 -> fp16 convert
// =====================================================================
__global__ __launch_bounds__(256) void cvt_kernel(
    const float* __restrict__ in, __half* __restrict__ out, int n4)
{
    int i = blockIdx.x * 256 + threadIdx.x;
    if (i >= n4) return;
    float4 v = ((const float4*)in)[i];
    ((__half2*)out)[2*i]   = __floats2half2_rn(v.x, v.y);
    ((__half2*)out)[2*i+1] = __floats2half2_rn(v.z, v.w);
}

// =====================================================================
// Prep: transpose + convert. w [rows, cols] -> t[c][r] (pitch opitch)
// =====================================================================
__global__ void transpose_cvt_kernel(
    const float* __restrict__ w, __half* __restrict__ t,
    int rows, int cols, int opitch)
{
    __shared__ float tile[32][33];
    int c0 = blockIdx.x * 32, r0 = blockIdx.y * 32;
    int tx = threadIdx.x, ty = threadIdx.y;
    #pragma unroll
    for (int i = 0; i < 4; i++)
        tile[ty + 8*i][tx] = w[(size_t)(r0 + ty + 8*i) * cols + c0 + tx];
    __syncthreads();
    #pragma unroll
    for (int i = 0; i < 4; i++)
        t[(size_t)(c0 + ty + 8*i) * opitch + r0 + tx] = __float2half_rn(tile[tx][ty + 8*i]);
}

// =====================================================================
// Prep: fill w2ext cols [2048, 2080): w_up rows then zeros
// =====================================================================
__global__ __launch_bounds__(256) void w2ext_extra_kernel(const float* __restrict__ w_up)
{
    int i = blockIdx.x * 256 + threadIdx.x;   // over 512*32
    int n = i >> 5, c = i & 31;
    float v = 0.0f;
    if (c < N_EXP * R_LORA) v = w_up[(size_t)c * D_IN + n];
    g_w2e[(size_t)n * K2 + D_HID + c] = __float2half_rn(v);
}

// =====================================================================
// Prep: w_down [E,D,R] -> wdt [32,512] fp16 (row n=e*8+r holds d-major)
// =====================================================================
__global__ __launch_bounds__(256) void wdt_prep_kernel(const float* __restrict__ w_down)
{
    int i = blockIdx.x * 256 + threadIdx.x;   // over 32*512
    int n = i >> 9, d = i & 511;
    float v = 0.0f;
    if (n < N_EXP * R_LORA) {
        int e = n >> 3, r = n & 7;
        v = w_down[(size_t)e * (D_IN * R_LORA) + (size_t)d * R_LORA + r];
    }
    g_wdt[(size_t)n * D_IN + d] = __float2half_rn(v);
}

// =====================================================================
// LoRA mini-GEMM: down = x @ wdt^T  [128 tok x 32], HMMA, then epilogue
// applies gelu * gate-weight (expert e == n8-tile j) and writes a24.
// Block 128 thr (4 warps, each 32 tok x 32), K=512, 3-buf cp.async.
// =====================================================================
#define LMAT_A 10240   // 128*80
#define LMAT_B 2560    // 32*80
#define LSTAGE (LMAT_A + LMAT_B)

__global__ __launch_bounds__(128) void lora_gemm_kernel(
    const __half* __restrict__ A,      // g_xh
    const __half* __restrict__ B,      // g_wdt
    const float* __restrict__ probs,   // [T,2]
    const int* __restrict__ idx)       // [T,2]
{
    __shared__ __align__(16) char sm[3 * LSTAGE];
    uint32_t sb = smem_to_u32(sm);

    int tid = threadIdx.x, lane = tid & 31, w = tid >> 5;
    int mBase = blockIdx.x * 128;

    // loaders: A 512 chunks/4 per thread; B 128 chunks/1 per thread
    const int NS = D_IN / 32;   // 16

    float acc[2][4][4];
    #pragma unroll
    for (int i = 0; i < 2; i++)
        #pragma unroll
        for (int j = 0; j < 4; j++)
            #pragma unroll
            for (int q = 0; q < 4; q++) acc[i][j][q] = 0.0f;

    auto issue = [&](int s) {
        uint32_t sbuf = sb + (uint32_t)(s % 3) * LSTAGE;
        int kt = s * 32;
        #pragma unroll
        for (int c = 0; c < 4; ++c) {
            int q = tid + 128 * c;
            int row = q >> 2, ch = q & 3;
            CP_ASYNC16(sbuf + (uint32_t)row * 80 + (uint32_t)ch * 16,
                       A + (size_t)(mBase + row) * D_IN + kt + ch * 8);
        }
        {
            int row = tid >> 2, ch = tid & 3;
            CP_ASYNC16(sbuf + LMAT_A + (uint32_t)row * 80 + (uint32_t)ch * 16,
                       B + (size_t)row * D_IN + kt + ch * 8);
        }
    };

    issue(0); CP_COMMIT();
    issue(1); CP_COMMIT();

    uint32_t a_off = (uint32_t)(w * 32 + (lane & 15)) * 80 + (uint32_t)((lane >> 4) * 8) * 2;
    uint32_t b_off = LMAT_A + (uint32_t)((lane & 7) + ((lane >> 4) << 3)) * 80
                   + (uint32_t)(((lane >> 3) & 1) * 8) * 2;

    #pragma unroll 1
    for (int s = 0; s < NS; ++s) {
        CP_WAIT1();
        __syncthreads();
        if (s + 2 < NS) issue(s + 2);
        CP_COMMIT();

        uint32_t buf = sb + (uint32_t)(s % 3) * LSTAGE;
        #pragma unroll
        for (int ks = 0; ks < 2; ++ks) {
            uint32_t kb = (uint32_t)ks * 32;
            uint32_t ah[2][4], bh[4][2];
            #pragma unroll
            for (int i = 0; i < 2; ++i)
                LDMATRIX_X4(ah[i][0], ah[i][1], ah[i][2], ah[i][3],
                            buf + a_off + (uint32_t)(i * 16) * 80 + kb);
            #pragma unroll
            for (int jj = 0; jj < 2; ++jj)
                LDMATRIX_X4(bh[2*jj][0], bh[2*jj][1], bh[2*jj+1][0], bh[2*jj+1][1],
                            buf + b_off + (uint32_t)(jj * 16) * 80 + kb);
            #pragma unroll
            for (int i = 0; i < 2; ++i)
                #pragma unroll
                for (int j = 0; j < 4; ++j)
                    MMA_FP16(acc[i][j], ah[i], bh[j][0], bh[j][1]);
        }
    }

    // epilogue: gate-weight + gelu, write a24 columns of g_h
    int g = lane >> 2, tq = lane & 3;
    #pragma unroll
    for (int i = 0; i < 2; ++i) {
        int t0 = mBase + w * 32 + i * 16 + g;
        int t1 = t0 + 8;
        int e00 = idx[2*t0], e01 = idx[2*t0+1];
        int e10 = idx[2*t1], e11 = idx[2*t1+1];
        float p00 = probs[2*t0], p01 = probs[2*t0+1];
        float p10 = probs[2*t1], p11 = probs[2*t1+1];
        #pragma unroll
        for (int j = 0; j < 3; ++j) {          // j == expert id; j=3 is pad
            float w0 = (e00 == j) ? p00 : ((e01 == j) ? p01 : 0.0f);
            float w1 = (e10 == j) ? p10 : ((e11 == j) ? p11 : 0.0f);
            float v0 = w0 * gelu_exact(acc[i][j][0]);
            float v1 = w0 * gelu_exact(acc[i][j][1]);
            float v2 = w1 * gelu_exact(acc[i][j][2]);
            float v3 = w1 * gelu_exact(acc[i][j][3]);
            int c = j * 8 + tq * 2;
            *(__half2*)(g_h + (size_t)t0 * K2 + D_HID + c) = __floats2half2_rn(v0, v1);
            *(__half2*)(g_h + (size_t)t1 * K2 + D_HID + c) = __floats2half2_rn(v2, v3);
        }
    }
}

// =====================================================================
// Main fp16 GEMM: CTA 128x256, 8 warps (warp tile 64x64), Kstage=32,
// 3-buffer cp.async pipeline, 1 CTA/SM.
// =====================================================================
#define MAT_A 10240          // 128*80
#define MAT_B 20480          // 256*80
#define STAGE_BYTES (MAT_A + MAT_B)
#define GSMEM_BYTES (3 * STAGE_BYTES + 1024)

template<int KTOT, int LDA, int LDB, bool IS_GEMM1>
__global__ __launch_bounds__(256, 1) void mma_gemm_kernel(
    const __half* __restrict__ A, const __half* __restrict__ B,
    const float* __restrict__ bias,
    __half* __restrict__ OutH, float* __restrict__ OutF)
{
    extern __shared__ char sm[];
    uint32_t sb = smem_to_u32(sm);
    float* bias_s = (float*)(sm + 3 * STAGE_BYTES);

    int tid = threadIdx.x, lane = tid & 31, wid = tid >> 5;
    int wm = wid >> 2, wn = wid & 3;          // warp grid 2(M) x 4(N)
    int nBase = blockIdx.x * 256, mBase = blockIdx.y * 128;

    bias_s[tid] = bias[nBase + tid];

    int lrow = tid >> 1;
    int lcc  = (tid & 1) * 2;
    size_t gArow = (size_t)(mBase + lrow) * LDA;
    size_t gBrow0 = (size_t)(nBase + lrow) * LDB;
    size_t gBrow1 = (size_t)(nBase + lrow + 128) * LDB;
    uint32_t soA  = (uint32_t)lrow * 80;
    uint32_t soB0 = MAT_A + (uint32_t)lrow * 80;
    uint32_t soB1 = MAT_A + (uint32_t)(lrow + 128) * 80;

    const int NS = KTOT / 32;

    float acc[4][8][4];
    #pragma unroll
    for (int i = 0; i < 4; i++)
        #pragma unroll
        for (int j = 0; j < 8; j++)
            #pragma unroll
            for (int q = 0; q < 4; q++) acc[i][j][q] = 0.0f;

    auto issue = [&](int s) {
        uint32_t sbuf = sb + (uint32_t)(s % 3) * STAGE_BYTES;
        int kt = s * 32;
        #pragma unroll
        for (int c = 0; c < 2; ++c) {
            uint32_t co = (uint32_t)(lcc + c) * 16;
            int ge = kt + (lcc + c) * 8;
            CP_ASYNC16(sbuf + soA  + co, A + gArow  + ge);
            CP_ASYNC16(sbuf + soB0 + co, B + gBrow0 + ge);
            CP_ASYNC16(sbuf + soB1 + co, B + gBrow1 + ge);
        }
    };

    issue(0); CP_COMMIT();
    issue(1); CP_COMMIT();

    uint32_t a_off = (uint32_t)(wm * 64 + (lane & 15)) * 80 + (uint32_t)((lane >> 4) * 8) * 2;
    uint32_t b_off = MAT_A + (uint32_t)(wn * 64 + (lane & 7) + ((lane >> 4) << 3)) * 80
                   + (uint32_t)(((lane >> 3) & 1) * 8) * 2;

    #pragma unroll 1
    for (int s = 0; s < NS; ++s) {
        CP_WAIT1();
        __syncthreads();
        if (s + 2 < NS) issue(s + 2);
        CP_COMMIT();

        uint32_t buf = sb + (uint32_t)(s % 3) * STAGE_BYTES;
        #pragma unroll
        for (int ks = 0; ks < 2; ++ks) {
            uint32_t kb = (uint32_t)ks * 32;
            uint32_t ah[4][4];
            #pragma unroll
            for (int i = 0; i < 4; ++i)
                LDMATRIX_X4(ah[i][0], ah[i][1], ah[i][2], ah[i][3],
                            buf + a_off + (uint32_t)(i * 16) * 80 + kb);
            uint32_t bh[8][2];
            #pragma unroll
            for (int jj = 0; jj < 4; ++jj)
                LDMATRIX_X4(bh[2*jj][0], bh[2*jj][1], bh[2*jj+1][0], bh[2*jj+1][1],
                            buf + b_off + (uint32_t)(jj * 16) * 80 + kb);
            #pragma unroll
            for (int i = 0; i < 4; ++i)
                #pragma unroll
                for (int j = 0; j < 8; ++j)
                    MMA_FP16(acc[i][j], ah[i], bh[j][0], bh[j][1]);
        }
    }

    // ---- epilogue ----
    int g = lane >> 2, tq = lane & 3;
    #pragma unroll
    for (int i = 0; i < 4; ++i) {
        int row0 = mBase + wm * 64 + i * 16 + g;
        int row1 = row0 + 8;
        #pragma unroll
        for (int j = 0; j < 8; ++j) {
            int nloc = wn * 64 + j * 8 + tq * 2;
            float b0 = bias_s[nloc], b1 = bias_s[nloc + 1];
            float v0 = acc[i][j][0] + b0, v1 = acc[i][j][1] + b1;
            float v2 = acc[i][j][2] + b0, v3 = acc[i][j][3] + b1;
            if (IS_GEMM1) {
                v0 = gelu_exact(v0); v1 = gelu_exact(v1);
                v2 = gelu_exact(v2); v3 = gelu_exact(v3);
                size_t o0 = (size_t)row0 * K2 + nBase + nloc;
                size_t o1 = (size_t)row1 * K2 + nBase + nloc;
                *(__half2*)(OutH + o0) = __floats2half2_rn(v0, v1);
                *(__half2*)(OutH + o1) = __floats2half2_rn(v2, v3);
            } else {
                size_t o0 = (size_t)row0 * D_IN + nBase + nloc;
                size_t o1 = (size_t)row1 * D_IN + nBase + nloc;
                *(float2*)(OutF + o0) = make_float2(v0, v1);
                *(float2*)(OutF + o1) = make_float2(v2, v3);
            }
        }
    }
}

// =====================================================================
// launch
// =====================================================================
extern "C" void kernel_launch(void* const* d_in, const int* in_sizes, int n_in,
                              void* d_out, int out_size) {
    const float* x          = (const float*)d_in[0];
    const float* W1         = (const float*)d_in[1];
    const float* b1         = (const float*)d_in[2];
    const float* W2         = (const float*)d_in[3];
    const float* b2         = (const float*)d_in[4];
    const float* w_down     = (const float*)d_in[5];
    const float* w_up       = (const float*)d_in[6];
    const float* topk_probs = (const float*)d_in[8];
    const int*   topk_idx   = (const int*)d_in[9];
    float* out = (float*)d_out;
    (void)in_sizes; (void)n_in; (void)out_size;

    __half *xh, *w1t, *w2e, *wdt, *hh;
    cudaGetSymbolAddress((void**)&xh,  g_xh);
    cudaGetSymbolAddress((void**)&w1t, g_w1t);
    cudaGetSymbolAddress((void**)&w2e, g_w2e);
    cudaGetSymbolAddress((void**)&wdt, g_wdt);
    cudaGetSymbolAddress((void**)&hh,  g_h);

    cudaFuncSetAttribute(mma_gemm_kernel<D_IN, D_IN, D_IN, true>,
                         cudaFuncAttributeMaxDynamicSharedMemorySize, GSMEM_BYTES);
    cudaFuncSetAttribute(mma_gemm_kernel<K2, K2, K2, false>,
                         cudaFuncAttributeMaxDynamicSharedMemorySize, GSMEM_BYTES);

    // prep
    int n4 = T_TOK * D_IN / 4;
    cvt_kernel<<<n4 / 256, 256>>>(x, xh, n4);
    transpose_cvt_kernel<<<dim3(D_HID / 32, D_IN / 32), dim3(32, 8)>>>(W1, w1t, D_IN, D_HID, D_IN);
    transpose_cvt_kernel<<<dim3(D_IN / 32, D_HID / 32), dim3(32, 8)>>>(W2, w2e, D_HID, D_IN, K2);
    w2ext_extra_kernel<<<(D_IN * 32) / 256, 256>>>(w_up);
    wdt_prep_kernel<<<(32 * D_IN) / 256, 256>>>(w_down);

    // lora a24 block (HMMA mini-GEMM)
    lora_gemm_kernel<<<T_TOK / 128, 128>>>(xh, wdt, topk_probs, topk_idx);

    // GEMM1: hidden = gelu(x @ W1 + b1) -> g_h (cols 0..2048)
    mma_gemm_kernel<D_IN, D_IN, D_IN, true>
        <<<dim3(D_HID / 256, T_TOK / 128), 256, GSMEM_BYTES>>>(
            xh, w1t, b1, hh, nullptr);

    // GEMM2: out = [hidden|a24] @ [W2;w_up] + b2
    mma_gemm_kernel<K2, K2, K2, false>
        <<<dim3(D_IN / 256, T_TOK / 128), 256, GSMEM_BYTES>>>(
            hh, w2e, b2, nullptr, out);
}

// round 7
// speedup vs baseline: 5.5044x; 1.1052x over previous
#include <cuda_runtime.h>
#include <cuda_fp16.h>
#include <cstdint>

// ---------------- problem constants ----------------
#define T_TOK 50176     // 64*28*28 tokens
#define D_IN  512
#define D_HID 2048
#define K2    2080      // D_HID + 24 moe cols + 8 zero pad
#define N_EXP 3
#define R_LORA 8

// ---------------- device scratch ----------------
__device__ __half g_xh[(size_t)T_TOK * D_IN];        // x in fp16
__device__ __half g_w1t[(size_t)D_HID * D_IN];       // W1^T [2048,512]
__device__ __half g_w2e[(size_t)D_IN * K2];          // [512,2080] = W2^T ++ w_up^T ++ 0
__device__ __half g_wdt[(size_t)32 * D_IN];          // w_down^T padded [32,512]
__device__ __half g_h[(size_t)T_TOK * K2];           // hidden ++ a24 ++ 0-pad

__device__ __forceinline__ float gelu_exact(float v) {
    return 0.5f * v * (1.0f + erff(v * 0.70710678118654752f));
}
__device__ __forceinline__ uint32_t smem_to_u32(const void* p) {
    uint32_t a;
    asm("{ .reg .u64 t; cvta.to.shared.u64 t, %1; cvt.u32.u64 %0, t; }" : "=r"(a) : "l"(p));
    return a;
}

// ---------------- base-ISA async copy / ldmatrix / mma helpers ----------
#define CP_ASYNC16(dst_smem, src_gmem) \
    asm volatile("cp.async.cg.shared.global [%0], [%1], 16;" \
        :: "r"(dst_smem), "l"(src_gmem) : "memory")
#define CP_COMMIT() asm volatile("cp.async.commit_group;" ::: "memory")
#define CP_WAIT1()  asm volatile("cp.async.wait_group 1;" ::: "memory")
#define CP_WAIT2()  asm volatile("cp.async.wait_group 2;" ::: "memory")

#define LDMATRIX_X4(r0, r1, r2, r3, addr) \
    asm volatile("ldmatrix.sync.aligned.m8n8.x4.shared.b16 {%0,%1,%2,%3}, [%4];" \
        : "=r"(r0), "=r"(r1), "=r"(r2), "=r"(r3) : "r"(addr))

#define MMA_FP16(c, a, b0_, b1_) \
    asm volatile("mma.sync.aligned.m16n8k16.row.col.f32.f16.f16.f32 " \
        "{%0,%1,%2,%3}, {%4,%5,%6,%7}, {%8,%9}, {%0,%1,%2,%3};" \
        : "+f"((c)[0]), "+f"((c)[1]), "+f"((c)[2]), "+f"((c)[3]) \
        : "r"((a)[0]), "r"((a)[1]), "r"((a)[2]), "r"((a)[3]), "r"(b0_), "r"(b1_))

// =====================================================================
// Prep: fp32 -> fp16 convert
// =====================================================================
__global__ __launch_bounds__(256) void cvt_kernel(
    const float* __restrict__ in, __half* __restrict__ out, int n4)
{
    int i = blockIdx.x * 256 + threadIdx.x;
    if (i >= n4) return;
    float4 v = ((const float4*)in)[i];
    ((__half2*)out)[2*i]   = __floats2half2_rn(v.x, v.y);
    ((__half2*)out)[2*i+1] = __floats2half2_rn(v.z, v.w);
}

// =====================================================================
// Prep: transpose + convert. w [rows, cols] -> t[c][r] (pitch opitch)
// =====================================================================
__global__ void transpose_cvt_kernel(
    const float* __restrict__ w, __half* __restrict__ t,
    int rows, int cols, int opitch)
{
    __shared__ float tile[32][33];
    int c0 = blockIdx.x * 32, r0 = blockIdx.y * 32;
    int tx = threadIdx.x, ty = threadIdx.y;
    #pragma unroll
    for (int i = 0; i < 4; i++)
        tile[ty + 8*i][tx] = w[(size_t)(r0 + ty + 8*i) * cols + c0 + tx];
    __syncthreads();
    #pragma unroll
    for (int i = 0; i < 4; i++)
        t[(size_t)(c0 + ty + 8*i) * opitch + r0 + tx] = __float2half_rn(tile[tx][ty + 8*i]);
}

// =====================================================================
// Prep (fused): w2ext extra cols + wdt
//   blocks [0,64):  fill g_w2e cols [2048,2080)  (512*32 elems)
//   blocks [64,128): fill g_wdt [32,512]         (32*512 elems)
// =====================================================================
__global__ __launch_bounds__(256) void prep_small_kernel(
    const float* __restrict__ w_up, const float* __restrict__ w_down)
{
    int b = blockIdx.x;
    if (b < 64) {
        int i = b * 256 + threadIdx.x;          // over 512*32
        int n = i >> 5, c = i & 31;
        float v = 0.0f;
        if (c < N_EXP * R_LORA) v = w_up[(size_t)c * D_IN + n];
        g_w2e[(size_t)n * K2 + D_HID + c] = __float2half_rn(v);
    } else {
        int i = (b - 64) * 256 + threadIdx.x;   // over 32*512
        int n = i >> 9, d = i & 511;
        float v = 0.0f;
        if (n < N_EXP * R_LORA) {
            int e = n >> 3, r = n & 7;
            v = w_down[(size_t)e * (D_IN * R_LORA) + (size_t)d * R_LORA + r];
        }
        g_wdt[(size_t)n * D_IN + d] = __float2half_rn(v);
    }
}

// =====================================================================
// LoRA mini-GEMM: down = x @ wdt^T [128 tok x 32] via HMMA; epilogue
// applies gelu * gate-weight (expert id == n8-tile j) and writes a24.
// =====================================================================
#define LMAT_A 10240   // 128*80
#define LMAT_B 2560    // 32*80
#define LSTAGE (LMAT_A + LMAT_B)

__global__ __launch_bounds__(128) void lora_gemm_kernel(
    const __half* __restrict__ A,      // g_xh
    const __half* __restrict__ B,      // g_wdt
    const float* __restrict__ probs,   // [T,2]
    const int* __restrict__ idx)       // [T,2]
{
    __shared__ __align__(16) char sm[3 * LSTAGE];
    uint32_t sb = smem_to_u32(sm);

    int tid = threadIdx.x, lane = tid & 31, w = tid >> 5;
    int mBase = blockIdx.x * 128;
    const int NS = D_IN / 32;   // 16

    float acc[2][4][4];
    #pragma unroll
    for (int i = 0; i < 2; i++)
        #pragma unroll
        for (int j = 0; j < 4; j++)
            #pragma unroll
            for (int q = 0; q < 4; q++) acc[i][j][q] = 0.0f;

    auto issue = [&](int s) {
        uint32_t sbuf = sb + (uint32_t)(s % 3) * LSTAGE;
        int kt = s * 32;
        #pragma unroll
        for (int c = 0; c < 4; ++c) {
            int q = tid + 128 * c;
            int row = q >> 2, ch = q & 3;
            CP_ASYNC16(sbuf + (uint32_t)row * 80 + (uint32_t)ch * 16,
                       A + (size_t)(mBase + row) * D_IN + kt + ch * 8);
        }
        {
            int row = tid >> 2, ch = tid & 3;
            CP_ASYNC16(sbuf + LMAT_A + (uint32_t)row * 80 + (uint32_t)ch * 16,
                       B + (size_t)row * D_IN + kt + ch * 8);
        }
    };

    issue(0); CP_COMMIT();
    issue(1); CP_COMMIT();

    uint32_t a_off = (uint32_t)(w * 32 + (lane & 15)) * 80 + (uint32_t)((lane >> 4) * 8) * 2;
    uint32_t b_off = LMAT_A + (uint32_t)((lane & 7) + ((lane >> 4) << 3)) * 80
                   + (uint32_t)(((lane >> 3) & 1) * 8) * 2;

    #pragma unroll 1
    for (int s = 0; s < NS; ++s) {
        CP_WAIT1();
        __syncthreads();
        if (s + 2 < NS) issue(s + 2);
        CP_COMMIT();

        uint32_t buf = sb + (uint32_t)(s % 3) * LSTAGE;
        #pragma unroll
        for (int ks = 0; ks < 2; ++ks) {
            uint32_t kb = (uint32_t)ks * 32;
            uint32_t ah[2][4], bh[4][2];
            #pragma unroll
            for (int i = 0; i < 2; ++i)
                LDMATRIX_X4(ah[i][0], ah[i][1], ah[i][2], ah[i][3],
                            buf + a_off + (uint32_t)(i * 16) * 80 + kb);
            #pragma unroll
            for (int jj = 0; jj < 2; ++jj)
                LDMATRIX_X4(bh[2*jj][0], bh[2*jj][1], bh[2*jj+1][0], bh[2*jj+1][1],
                            buf + b_off + (uint32_t)(jj * 16) * 80 + kb);
            #pragma unroll
            for (int i = 0; i < 2; ++i)
                #pragma unroll
                for (int j = 0; j < 4; ++j)
                    MMA_FP16(acc[i][j], ah[i], bh[j][0], bh[j][1]);
        }
    }

    int g = lane >> 2, tq = lane & 3;
    #pragma unroll
    for (int i = 0; i < 2; ++i) {
        int t0 = mBase + w * 32 + i * 16 + g;
        int t1 = t0 + 8;
        int e00 = idx[2*t0], e01 = idx[2*t0+1];
        int e10 = idx[2*t1], e11 = idx[2*t1+1];
        float p00 = probs[2*t0], p01 = probs[2*t0+1];
        float p10 = probs[2*t1], p11 = probs[2*t1+1];
        #pragma unroll
        for (int j = 0; j < 3; ++j) {
            float w0 = (e00 == j) ? p00 : ((e01 == j) ? p01 : 0.0f);
            float w1 = (e10 == j) ? p10 : ((e11 == j) ? p11 : 0.0f);
            float v0 = w0 * gelu_exact(acc[i][j][0]);
            float v1 = w0 * gelu_exact(acc[i][j][1]);
            float v2 = w1 * gelu_exact(acc[i][j][2]);
            float v3 = w1 * gelu_exact(acc[i][j][3]);
            int c = j * 8 + tq * 2;
            *(__half2*)(g_h + (size_t)t0 * K2 + D_HID + c) = __floats2half2_rn(v0, v1);
            *(__half2*)(g_h + (size_t)t1 * K2 + D_HID + c) = __floats2half2_rn(v2, v3);
        }
    }
}

// =====================================================================
// Main fp16 GEMM (round-5 proven config): CTA 128x128, 8 warps
// (warp tile 64x32), Kstage=32, 4-buffer / depth-3 cp.async, 2 CTA/SM.
// =====================================================================
#define MAT_BYTES 10240     // 128 * 40 * 2
#define STAGE_BYTES 20480
#define GSMEM_BYTES (4 * STAGE_BYTES + 512)

template<int KTOT, int LDA, int LDB, bool IS_GEMM1>
__global__ __launch_bounds__(256, 2) void mma_gemm_kernel(
    const __half* __restrict__ A, const __half* __restrict__ B,
    const float* __restrict__ bias,
    __half* __restrict__ OutH, float* __restrict__ OutF)
{
    extern __shared__ char sm[];
    uint32_t sb = smem_to_u32(sm);
    float* bias_s = (float*)(sm + 4 * STAGE_BYTES);

    int tid = threadIdx.x, lane = tid & 31, wid = tid >> 5;
    int wm = wid >> 2, wn = wid & 3;          // warp grid 2 x 4
    int nBase = blockIdx.x * 128, mBase = blockIdx.y * 128;

    if (tid < 128) bias_s[tid] = bias[nBase + tid];

    int lrow = tid >> 1;
    int lcc  = (tid & 1) * 2;
    size_t gArow = (size_t)(mBase + lrow) * LDA;
    size_t gBrow = (size_t)(nBase + lrow) * LDB;
    uint32_t srowoff = (uint32_t)lrow * 80;

    const int NS = KTOT / 32;

    float acc[4][4][4];
    #pragma unroll
    for (int i = 0; i < 4; i++)
        #pragma unroll
        for (int j = 0; j < 4; j++)
            #pragma unroll
            for (int q = 0; q < 4; q++) acc[i][j][q] = 0.0f;

    // prologue: stages 0..2
    #pragma unroll
    for (int p = 0; p < 3; ++p) {
        if (p < NS) {
            uint32_t sbuf = sb + (uint32_t)p * STAGE_BYTES;
            int kt = p * 32;
            #pragma unroll
            for (int c = 0; c < 2; ++c) {
                uint32_t so = srowoff + (uint32_t)(lcc + c) * 16;
                int ge = kt + (lcc + c) * 8;
                CP_ASYNC16(sbuf +             so, A + gArow + ge);
                CP_ASYNC16(sbuf + MAT_BYTES + so, B + gBrow + ge);
            }
        }
        CP_COMMIT();
    }

    uint32_t a_off = (uint32_t)(wm * 64 + (lane & 15)) * 80 + (uint32_t)((lane >> 4) * 8) * 2;
    uint32_t b_off = (uint32_t)(wn * 32 + (lane & 7) + ((lane >> 4) << 3)) * 80
                   + (uint32_t)(((lane >> 3) & 1) * 8) * 2;

    #pragma unroll 1
    for (int s = 0; s < NS; ++s) {
        CP_WAIT2();
        __syncthreads();

        if (s + 3 < NS) {
            uint32_t sbuf = sb + (uint32_t)((s + 3) & 3) * STAGE_BYTES;
            int kt = (s + 3) * 32;
            #pragma unroll
            for (int c = 0; c < 2; ++c) {
                uint32_t so = srowoff + (uint32_t)(lcc + c) * 16;
                int ge = kt + (lcc + c) * 8;
                CP_ASYNC16(sbuf +             so, A + gArow + ge);
                CP_ASYNC16(sbuf + MAT_BYTES + so, B + gBrow + ge);
            }
        }
        CP_COMMIT();

        uint32_t buf = sb + (uint32_t)(s & 3) * STAGE_BYTES;
        #pragma unroll
        for (int ks = 0; ks < 2; ++ks) {
            uint32_t kb = (uint32_t)(ks * 16) * 2;
            uint32_t ah[4][4];
            #pragma unroll
            for (int i = 0; i < 4; ++i) {
                uint32_t ad = buf + a_off + (uint32_t)(i * 16) * 80 + kb;
                LDMATRIX_X4(ah[i][0], ah[i][1], ah[i][2], ah[i][3], ad);
            }
            uint32_t bh[4][2];
            #pragma unroll
            for (int jj = 0; jj < 2; ++jj) {
                uint32_t bd = buf + MAT_BYTES + b_off + (uint32_t)(jj * 16) * 80 + kb;
                LDMATRIX_X4(bh[2*jj][0], bh[2*jj][1], bh[2*jj+1][0], bh[2*jj+1][1], bd);
            }
            #pragma unroll
            for (int i = 0; i < 4; ++i)
                #pragma unroll
                for (int j = 0; j < 4; ++j)
                    MMA_FP16(acc[i][j], ah[i], bh[j][0], bh[j][1]);
        }
    }

    // epilogue
    int g = lane >> 2, tq = lane & 3;
    #pragma unroll
    for (int i = 0; i < 4; ++i) {
        int row0 = mBase + wm * 64 + i * 16 + g;
        int row1 = row0 + 8;
        #pragma unroll
        for (int j = 0; j < 4; ++j) {
            int nloc = wn * 32 + j * 8 + tq * 2;
            float b0 = bias_s[nloc], b1 = bias_s[nloc + 1];
            float v0 = acc[i][j][0] + b0, v1 = acc[i][j][1] + b1;
            float v2 = acc[i][j][2] + b0, v3 = acc[i][j][3] + b1;
            if (IS_GEMM1) {
                v0 = gelu_exact(v0); v1 = gelu_exact(v1);
                v2 = gelu_exact(v2); v3 = gelu_exact(v3);
                size_t o0 = (size_t)row0 * K2 + nBase + nloc;
                size_t o1 = (size_t)row1 * K2 + nBase + nloc;
                *(__half2*)(OutH + o0) = __floats2half2_rn(v0, v1);
                *(__half2*)(OutH + o1) = __floats2half2_rn(v2, v3);
            } else {
                size_t o0 = (size_t)row0 * D_IN + nBase + nloc;
                size_t o1 = (size_t)row1 * D_IN + nBase + nloc;
                *(float2*)(OutF + o0) = make_float2(v0, v1);
                *(float2*)(OutF + o1) = make_float2(v2, v3);
            }
        }
    }
}

// =====================================================================
// launch
// =====================================================================
extern "C" void kernel_launch(void* const* d_in, const int* in_sizes, int n_in,
                              void* d_out, int out_size) {
    const float* x          = (const float*)d_in[0];
    const float* W1         = (const float*)d_in[1];
    const float* b1         = (const float*)d_in[2];
    const float* W2         = (const float*)d_in[3];
    const float* b2         = (const float*)d_in[4];
    const float* w_down     = (const float*)d_in[5];
    const float* w_up       = (const float*)d_in[6];
    const float* topk_probs = (const float*)d_in[8];
    const int*   topk_idx   = (const int*)d_in[9];
    float* out = (float*)d_out;
    (void)in_sizes; (void)n_in; (void)out_size;

    __half *xh, *w1t, *w2e, *wdt, *hh;
    cudaGetSymbolAddress((void**)&xh,  g_xh);
    cudaGetSymbolAddress((void**)&w1t, g_w1t);
    cudaGetSymbolAddress((void**)&w2e, g_w2e);
    cudaGetSymbolAddress((void**)&wdt, g_wdt);
    cudaGetSymbolAddress((void**)&hh,  g_h);

    cudaFuncSetAttribute(mma_gemm_kernel<D_IN, D_IN, D_IN, true>,
                         cudaFuncAttributeMaxDynamicSharedMemorySize, GSMEM_BYTES);
    cudaFuncSetAttribute(mma_gemm_kernel<K2, K2, K2, false>,
                         cudaFuncAttributeMaxDynamicSharedMemorySize, GSMEM_BYTES);

    // prep
    int n4 = T_TOK * D_IN / 4;
    cvt_kernel<<<n4 / 256, 256>>>(x, xh, n4);
    transpose_cvt_kernel<<<dim3(D_HID / 32, D_IN / 32), dim3(32, 8)>>>(W1, w1t, D_IN, D_HID, D_IN);
    transpose_cvt_kernel<<<dim3(D_IN / 32, D_HID / 32), dim3(32, 8)>>>(W2, w2e, D_HID, D_IN, K2);
    prep_small_kernel<<<128, 256>>>(w_up, w_down);

    // lora a24 block (HMMA mini-GEMM)
    lora_gemm_kernel<<<T_TOK / 128, 128>>>(xh, wdt, topk_probs, topk_idx);

    // GEMM1: hidden = gelu(x @ W1 + b1) -> g_h (cols 0..2048)
    mma_gemm_kernel<D_IN, D_IN, D_IN, true>
        <<<dim3(D_HID / 128, T_TOK / 128), 256, GSMEM_BYTES>>>(
            xh, w1t, b1, hh, nullptr);

    // GEMM2: out = [hidden|a24] @ [W2;w_up] + b2
    mma_gemm_kernel<K2, K2, K2, false>
        <<<dim3(D_IN / 128, T_TOK / 128), 256, GSMEM_BYTES>>>(
            hh, w2e, b2, nullptr, out);
}

// round 9
// speedup vs baseline: 5.6475x; 1.0260x over previous
#include <cuda_runtime.h>
#include <cuda_fp16.h>
#include <cstdint>

// ---------------- problem constants ----------------
#define T_TOK 50176     // 64*28*28 tokens
#define D_IN  512
#define D_HID 2048
#define K2    2080      // D_HID + 24 moe cols + 8 zero pad
#define N_EXP 3
#define R_LORA 8

#define NROW  392       // token row-blocks of 128
#define NJOBS 8232      // 392 lora + 6272 gemm1 + 1568 gemm2

// ---------------- device scratch ----------------
__device__ __half g_xh[(size_t)T_TOK * D_IN];        // x in fp16
__device__ __half g_w1t[(size_t)D_HID * D_IN];       // W1^T [2048,512]
__device__ __half g_w2e[(size_t)D_IN * K2];          // [512,2080] = W2^T ++ w_up^T ++ 0
__device__ __half g_wdt[(size_t)32 * D_IN];          // w_down^T padded [32,512]
__device__ __half g_h[(size_t)T_TOK * K2];           // hidden ++ a24 ++ 0-pad
__device__ int    g_ticket;
__device__ int    g_rowdone[NROW];

__device__ __forceinline__ float gelu_exact(float v) {
    return 0.5f * v * (1.0f + erff(v * 0.70710678118654752f));
}
__device__ __forceinline__ uint32_t smem_to_u32(const void* p) {
    uint32_t a;
    asm("{ .reg .u64 t; cvta.to.shared.u64 t, %1; cvt.u32.u64 %0, t; }" : "=r"(a) : "l"(p));
    return a;
}

// ---------------- base-ISA async copy / ldmatrix / mma helpers ----------
#define CP_ASYNC16(dst_smem, src_gmem) \
    asm volatile("cp.async.cg.shared.global [%0], [%1], 16;" \
        :: "r"(dst_smem), "l"(src_gmem) : "memory")
#define CP_COMMIT() asm volatile("cp.async.commit_group;" ::: "memory")
#define CP_WAIT1()  asm volatile("cp.async.wait_group 1;" ::: "memory")
#define CP_WAIT2()  asm volatile("cp.async.wait_group 2;" ::: "memory")

#define LDMATRIX_X4(r0, r1, r2, r3, addr) \
    asm volatile("ldmatrix.sync.aligned.m8n8.x4.shared.b16 {%0,%1,%2,%3}, [%4];" \
        : "=r"(r0), "=r"(r1), "=r"(r2), "=r"(r3) : "r"(addr))

#define MMA_FP16(c, a, b0_, b1_) \
    asm volatile("mma.sync.aligned.m16n8k16.row.col.f32.f16.f16.f32 " \
        "{%0,%1,%2,%3}, {%4,%5,%6,%7}, {%8,%9}, {%0,%1,%2,%3};" \
        : "+f"((c)[0]), "+f"((c)[1]), "+f"((c)[2]), "+f"((c)[3]) \
        : "r"((a)[0]), "r"((a)[1]), "r"((a)[2]), "r"((a)[3]), "r"(b0_), "r"(b1_))

// =====================================================================
// Reset: zero scheduler state (must run each launch; graph replays)
// =====================================================================
__global__ void reset_kernel() {
    int i = threadIdx.x;
    if (i == 0) g_ticket = 0;
    for (int j = i; j < NROW; j += blockDim.x) g_rowdone[j] = 0;
}

// =====================================================================
// Prep: fp32 -> fp16 convert (x)
// =====================================================================
__global__ __launch_bounds__(256) void cvt_kernel(
    const float* __restrict__ in, __half* __restrict__ out, int n4)
{
    int i = blockIdx.x * 256 + threadIdx.x;
    if (i >= n4) return;
    float4 v = ((const float4*)in)[i];
    ((__half2*)out)[2*i]   = __floats2half2_rn(v.x, v.y);
    ((__half2*)out)[2*i+1] = __floats2half2_rn(v.z, v.w);
}

// =====================================================================
// Prep (fused): W1^T, W2^T, w2ext extra cols, wdt — one launch
// =====================================================================
__global__ __launch_bounds__(256) void prep_weights_kernel(
    const float* __restrict__ W1, const float* __restrict__ W2,
    const float* __restrict__ w_up, const float* __restrict__ w_down)
{
    __shared__ float tile[32][33];
    int b = blockIdx.x;
    int tx = threadIdx.x & 31, ty = threadIdx.x >> 5;
    if (b < 1024) {
        int c0 = (b & 63) * 32, r0 = (b >> 6) * 32;   // cols of W1 (2048), rows (512)
        #pragma unroll
        for (int i = 0; i < 4; i++)
            tile[ty + 8*i][tx] = W1[(size_t)(r0 + ty + 8*i) * D_HID + c0 + tx];
        __syncthreads();
        #pragma unroll
        for (int i = 0; i < 4; i++)
            g_w1t[(size_t)(c0 + ty + 8*i) * D_IN + r0 + tx] = __float2half_rn(tile[tx][ty + 8*i]);
    } else if (b < 2048) {
        int b2 = b - 1024;
        int c0 = (b2 & 15) * 32, r0 = (b2 >> 4) * 32; // cols of W2 (512), rows (2048)
        #pragma unroll
        for (int i = 0; i < 4; i++)
            tile[ty + 8*i][tx] = W2[(size_t)(r0 + ty + 8*i) * D_IN + c0 + tx];
        __syncthreads();
        #pragma unroll
        for (int i = 0; i < 4; i++)
            g_w2e[(size_t)(c0 + ty + 8*i) * K2 + r0 + tx] = __float2half_rn(tile[tx][ty + 8*i]);
    } else {
        int b3 = b - 2048;
        if (b3 < 64) {
            int i = b3 * 256 + threadIdx.x;          // over 512*32
            int n = i >> 5, c = i & 31;
            float v = 0.0f;
            if (c < N_EXP * R_LORA) v = w_up[(size_t)c * D_IN + n];
            g_w2e[(size_t)n * K2 + D_HID + c] = __float2half_rn(v);
        } else {
            int i = (b3 - 64) * 256 + threadIdx.x;   // over 32*512
            int n = i >> 9, d = i & 511;
            float v = 0.0f;
            if (n < N_EXP * R_LORA) {
                int e = n >> 3, r = n & 7;
                v = w_down[(size_t)e * (D_IN * R_LORA) + (size_t)d * R_LORA + r];
            }
            g_wdt[(size_t)n * D_IN + d] = __float2half_rn(v);
        }
    }
}

// =====================================================================
// Mega-kernel pieces
// =====================================================================
#define MAT_BYTES 10240     // 128 * 40 * 2
#define STAGE_BYTES 20480
#define GSMEM_BYTES (4 * STAGE_BYTES + 512)

#define LMAT_A 10240
#define LSTAGE 12800

// --- LoRA job: down = x @ wdt^T [128 tok x 32], gated-gelu epilogue ---
__device__ void do_lora(int m, const float* __restrict__ probs,
                        const int* __restrict__ idx, char* sm, int tid)
{
    uint32_t sb = smem_to_u32(sm);
    int lane = tid & 31, w = tid >> 5;     // 8 warps, warp = one m16 tile
    int mBase = m * 128;
    const int NS = D_IN / 32;              // 16

    float acc[4][4];
    #pragma unroll
    for (int j = 0; j < 4; j++)
        #pragma unroll
        for (int q = 0; q < 4; q++) acc[j][q] = 0.0f;

    auto issue = [&](int s) {
        uint32_t sbuf = sb + (uint32_t)(s % 3) * LSTAGE;
        int kt = s * 32;
        // A: 128 rows x 4 chunks = 512 chunks over 256 threads (2/thread)
        #pragma unroll
        for (int c = 0; c < 2; ++c) {
            int q = tid + 256 * c;
            int row = q >> 2, ch = q & 3;
            CP_ASYNC16(sbuf + (uint32_t)row * 80 + (uint32_t)ch * 16,
                       g_xh + (size_t)(mBase + row) * D_IN + kt + ch * 8);
        }
        // B: 32 rows x 4 chunks = 128 chunks (tid < 128)
        if (tid < 128) {
            int row = tid >> 2, ch = tid & 3;
            CP_ASYNC16(sbuf + LMAT_A + (uint32_t)row * 80 + (uint32_t)ch * 16,
                       g_wdt + (size_t)row * D_IN + kt + ch * 8);
        }
    };

    issue(0); CP_COMMIT();
    issue(1); CP_COMMIT();

    uint32_t a_off = (uint32_t)(w * 16 + (lane & 15)) * 80 + (uint32_t)((lane >> 4) * 8) * 2;
    uint32_t b_off = LMAT_A + (uint32_t)((lane & 7) + ((lane >> 4) << 3)) * 80
                   + (uint32_t)(((lane >> 3) & 1) * 8) * 2;

    #pragma unroll 1
    for (int s = 0; s < NS; ++s) {
        CP_WAIT1();
        __syncthreads();
        if (s + 2 < NS) issue(s + 2);
        CP_COMMIT();

        uint32_t buf = sb + (uint32_t)(s % 3) * LSTAGE;
        #pragma unroll
        for (int ks = 0; ks < 2; ++ks) {
            uint32_t kb = (uint32_t)ks * 32;
            uint32_t ah[4], bh[4][2];
            LDMATRIX_X4(ah[0], ah[1], ah[2], ah[3], buf + a_off + kb);
            #pragma unroll
            for (int jj = 0; jj < 2; ++jj)
                LDMATRIX_X4(bh[2*jj][0], bh[2*jj][1], bh[2*jj+1][0], bh[2*jj+1][1],
                            buf + b_off + (uint32_t)(jj * 16) * 80 + kb);
            #pragma unroll
            for (int j = 0; j < 4; ++j)
                MMA_FP16(acc[j], ah, bh[j][0], bh[j][1]);
        }
    }
    __syncthreads();   // reads done before smem reuse by next job

    int g = lane >> 2, tq = lane & 3;
    int t0 = mBase + w * 16 + g;
    int t1 = t0 + 8;
    int e00 = idx[2*t0], e01 = idx[2*t0+1];
    int e10 = idx[2*t1], e11 = idx[2*t1+1];
    float p00 = probs[2*t0], p01 = probs[2*t0+1];
    float p10 = probs[2*t1], p11 = probs[2*t1+1];
    #pragma unroll
    for (int j = 0; j < 3; ++j) {          // j == expert id
        float w0 = (e00 == j) ? p00 : ((e01 == j) ? p01 : 0.0f);
        float w1 = (e10 == j) ? p10 : ((e11 == j) ? p11 : 0.0f);
        float v0 = w0 * gelu_exact(acc[j][0]);
        float v1 = w0 * gelu_exact(acc[j][1]);
        float v2 = w1 * gelu_exact(acc[j][2]);
        float v3 = w1 * gelu_exact(acc[j][3]);
        int c = j * 8 + tq * 2;
        *(__half2*)(g_h + (size_t)t0 * K2 + D_HID + c) = __floats2half2_rn(v0, v1);
        *(__half2*)(g_h + (size_t)t1 * K2 + D_HID + c) = __floats2half2_rn(v2, v3);
    }
}

// --- GEMM job: CTA 128x128, 8 warps (64x32), 4-buf depth-3 cp.async ---
template<int KTOT, int LD, bool IS_GEMM1>
__device__ void do_gemm(int mBase, int nBase,
                        const __half* __restrict__ A, const __half* __restrict__ B,
                        const float* __restrict__ bias,
                        __half* __restrict__ OutH, float* __restrict__ OutF,
                        char* sm, int tid)
{
    uint32_t sb = smem_to_u32(sm);
    float* bias_s = (float*)(sm + 4 * STAGE_BYTES);

    int lane = tid & 31, wid = tid >> 5;
    int wm = wid >> 2, wn = wid & 3;

    if (tid < 128) bias_s[tid] = bias[nBase + tid];

    int lrow = tid >> 1;
    int lcc  = (tid & 1) * 2;
    size_t gArow = (size_t)(mBase + lrow) * LD;
    size_t gBrow = (size_t)(nBase + lrow) * LD;
    uint32_t srowoff = (uint32_t)lrow * 80;

    const int NS = KTOT / 32;

    float acc[4][4][4];
    #pragma unroll
    for (int i = 0; i < 4; i++)
        #pragma unroll
        for (int j = 0; j < 4; j++)
            #pragma unroll
            for (int q = 0; q < 4; q++) acc[i][j][q] = 0.0f;

    #pragma unroll
    for (int p = 0; p < 3; ++p) {
        if (p < NS) {
            uint32_t sbuf = sb + (uint32_t)p * STAGE_BYTES;
            int kt = p * 32;
            #pragma unroll
            for (int c = 0; c < 2; ++c) {
                uint32_t so = srowoff + (uint32_t)(lcc + c) * 16;
                int ge = kt + (lcc + c) * 8;
                CP_ASYNC16(sbuf +             so, A + gArow + ge);
                CP_ASYNC16(sbuf + MAT_BYTES + so, B + gBrow + ge);
            }
        }
        CP_COMMIT();
    }

    uint32_t a_off = (uint32_t)(wm * 64 + (lane & 15)) * 80 + (uint32_t)((lane >> 4) * 8) * 2;
    uint32_t b_off = (uint32_t)(wn * 32 + (lane & 7) + ((lane >> 4) << 3)) * 80
                   + (uint32_t)(((lane >> 3) & 1) * 8) * 2;

    #pragma unroll 1
    for (int s = 0; s < NS; ++s) {
        CP_WAIT2();
        __syncthreads();

        if (s + 3 < NS) {
            uint32_t sbuf = sb + (uint32_t)((s + 3) & 3) * STAGE_BYTES;
            int kt = (s + 3) * 32;
            #pragma unroll
            for (int c = 0; c < 2; ++c) {
                uint32_t so = srowoff + (uint32_t)(lcc + c) * 16;
                int ge = kt + (lcc + c) * 8;
                CP_ASYNC16(sbuf +             so, A + gArow + ge);
                CP_ASYNC16(sbuf + MAT_BYTES + so, B + gBrow + ge);
            }
        }
        CP_COMMIT();

        uint32_t buf = sb + (uint32_t)(s & 3) * STAGE_BYTES;
        #pragma unroll
        for (int ks = 0; ks < 2; ++ks) {
            uint32_t kb = (uint32_t)(ks * 16) * 2;
            uint32_t ah[4][4];
            #pragma unroll
            for (int i = 0; i < 4; ++i)
                LDMATRIX_X4(ah[i][0], ah[i][1], ah[i][2], ah[i][3],
                            buf + a_off + (uint32_t)(i * 16) * 80 + kb);
            uint32_t bh[4][2];
            #pragma unroll
            for (int jj = 0; jj < 2; ++jj)
                LDMATRIX_X4(bh[2*jj][0], bh[2*jj][1], bh[2*jj+1][0], bh[2*jj+1][1],
                            buf + MAT_BYTES + b_off + (uint32_t)(jj * 16) * 80 + kb);
            #pragma unroll
            for (int i = 0; i < 4; ++i)
                #pragma unroll
                for (int j = 0; j < 4; ++j)
                    MMA_FP16(acc[i][j], ah[i], bh[j][0], bh[j][1]);
        }
    }
    __syncthreads();   // reads done before next job's loads overwrite smem

    int g = lane >> 2, tq = lane & 3;
    #pragma unroll
    for (int i = 0; i < 4; ++i) {
        int row0 = mBase + wm * 64 + i * 16 + g;
        int row1 = row0 + 8;
        #pragma unroll
        for (int j = 0; j < 4; ++j) {
            int nloc = wn * 32 + j * 8 + tq * 2;
            float b0 = bias_s[nloc], b1 = bias_s[nloc + 1];
            float v0 = acc[i][j][0] + b0, v1 = acc[i][j][1] + b1;
            float v2 = acc[i][j][2] + b0, v3 = acc[i][j][3] + b1;
            if (IS_GEMM1) {
                v0 = gelu_exact(v0); v1 = gelu_exact(v1);
                v2 = gelu_exact(v2); v3 = gelu_exact(v3);
                size_t o0 = (size_t)row0 * K2 + nBase + nloc;
                size_t o1 = (size_t)row1 * K2 + nBase + nloc;
                *(__half2*)(OutH + o0) = __floats2half2_rn(v0, v1);
                *(__half2*)(OutH + o1) = __floats2half2_rn(v2, v3);
            } else {
                size_t o0 = (size_t)row0 * D_IN + nBase + nloc;
                size_t o1 = (size_t)row1 * D_IN + nBase + nloc;
                *(float2*)(OutF + o0) = make_float2(v0, v1);
                *(float2*)(OutF + o1) = make_float2(v2, v3);
            }
        }
    }
}

// --- persistent scheduler ---
__global__ __launch_bounds__(256, 2) void mega_kernel(
    const float* __restrict__ b1, const float* __restrict__ b2,
    const float* __restrict__ probs, const int* __restrict__ idx,
    float* __restrict__ out)
{
    extern __shared__ char sm[];
    __shared__ int s_job;
    int tid = threadIdx.x;

    for (;;) {
        __syncthreads();
        if (tid == 0) s_job = atomicAdd(&g_ticket, 1);
        __syncthreads();
        int job = s_job;
        if (job >= NJOBS) return;

        int type, m, n = 0;
        if (job < 392) { type = 0; m = job; }
        else {
            int j = job - 392;
            if (j < 768) { type = 1; m = j >> 4; n = j & 15; }
            else if (j < 7648) {
                int t = j - 768, b = t / 20, r = t % 20;
                if (r < 16) { type = 1; m = 48 + b; n = r; }
                else        { type = 2; m = b;      n = r - 16; }
            } else {
                int t = j - 7648; type = 2; m = 344 + (t >> 2); n = t & 3;
            }
        }

        if (type == 0) {
            do_lora(m, probs, idx, sm, tid);
            __threadfence();
            __syncthreads();
            if (tid == 0) atomicAdd(&g_rowdone[m], 1);
        } else if (type == 1) {
            do_gemm<D_IN, D_IN, true>(m * 128, n * 128, g_xh, g_w1t, b1,
                                      g_h, nullptr, sm, tid);
            __threadfence();
            __syncthreads();
            if (tid == 0) atomicAdd(&g_rowdone[m], 1);
        } else {
            if (tid == 0) {
                while (atomicAdd(&g_rowdone[m], 0) < 17) __nanosleep(128);
            }
            __syncthreads();
            __threadfence();
            do_gemm<K2, K2, false>(m * 128, n * 128, g_h, g_w2e, b2,
                                   nullptr, out, sm, tid);
        }
    }
}

// =====================================================================
// launch
// =====================================================================
extern "C" void kernel_launch(void* const* d_in, const int* in_sizes, int n_in,
                              void* d_out, int out_size) {
    const float* x          = (const float*)d_in[0];
    const float* W1         = (const float*)d_in[1];
    const float* b1         = (const float*)d_in[2];
    const float* W2         = (const float*)d_in[3];
    const float* b2         = (const float*)d_in[4];
    const float* w_down     = (const float*)d_in[5];
    const float* w_up       = (const float*)d_in[6];
    const float* topk_probs = (const float*)d_in[8];
    const int*   topk_idx   = (const int*)d_in[9];
    float* out = (float*)d_out;
    (void)in_sizes; (void)n_in; (void)out_size;

    __half* xh;
    cudaGetSymbolAddress((void**)&xh, g_xh);

    cudaFuncSetAttribute(mega_kernel,
                         cudaFuncAttributeMaxDynamicSharedMemorySize, GSMEM_BYTES);

    reset_kernel<<<1, 512>>>();

    int n4 = T_TOK * D_IN / 4;
    cvt_kernel<<<n4 / 256, 256>>>(x, xh, n4);
    prep_weights_kernel<<<2176, 256>>>(W1, W2, w_up, w_down);

    mega_kernel<<<304, 256, GSMEM_BYTES>>>(b1, b2, topk_probs, topk_idx, out);
}

// round 10
// speedup vs baseline: 6.3467x; 1.1238x over previous
#include <cuda_runtime.h>
#include <cuda_fp16.h>
#include <cstdint>

// ---------------- problem constants ----------------
#define T_TOK 50176     // 64*28*28 tokens
#define D_IN  512
#define D_HID 2048
#define K2    2080      // D_HID + 24 moe cols + 8 zero pad
#define N_EXP 3
#define R_LORA 8

#define NROW  392       // token row-blocks of 128
#define NJOBS 8232      // 392 lora + 6272 gemm1 + 1568 gemm2

// ---------------- device scratch ----------------
__device__ __half g_xh[(size_t)T_TOK * D_IN];        // x in fp16
__device__ __half g_w1t[(size_t)D_HID * D_IN];       // W1^T [2048,512]
__device__ __half g_w2e[(size_t)D_IN * K2];          // [512,2080] = W2^T ++ w_up^T ++ 0
__device__ __half g_wdt[(size_t)32 * D_IN];          // w_down^T padded [32,512]
__device__ __half g_h[(size_t)T_TOK * K2];           // hidden ++ a24 ++ 0-pad
__device__ int    g_ticket;
__device__ int    g_rowdone[NROW];

__device__ __forceinline__ float gelu_exact(float v) {
    return 0.5f * v * (1.0f + erff(v * 0.70710678118654752f));
}
__device__ __forceinline__ uint32_t smem_to_u32(const void* p) {
    uint32_t a;
    asm("{ .reg .u64 t; cvta.to.shared.u64 t, %1; cvt.u32.u64 %0, t; }" : "=r"(a) : "l"(p));
    return a;
}

// ---------------- base-ISA async copy / ldmatrix / mma helpers ----------
#define CP_ASYNC16(dst_smem, src_gmem) \
    asm volatile("cp.async.cg.shared.global [%0], [%1], 16;" \
        :: "r"(dst_smem), "l"(src_gmem) : "memory")
#define CP_COMMIT() asm volatile("cp.async.commit_group;" ::: "memory")
#define CP_WAIT1()  asm volatile("cp.async.wait_group 1;" ::: "memory")

#define LDMATRIX_X4(r0, r1, r2, r3, addr) \
    asm volatile("ldmatrix.sync.aligned.m8n8.x4.shared.b16 {%0,%1,%2,%3}, [%4];" \
        : "=r"(r0), "=r"(r1), "=r"(r2), "=r"(r3) : "r"(addr))

#define MMA_FP16(c, a, b0_, b1_) \
    asm volatile("mma.sync.aligned.m16n8k16.row.col.f32.f16.f16.f32 " \
        "{%0,%1,%2,%3}, {%4,%5,%6,%7}, {%8,%9}, {%0,%1,%2,%3};" \
        : "+f"((c)[0]), "+f"((c)[1]), "+f"((c)[2]), "+f"((c)[3]) \
        : "r"((a)[0]), "r"((a)[1]), "r"((a)[2]), "r"((a)[3]), "r"(b0_), "r"(b1_))

// =====================================================================
// Reset: zero scheduler state (must run each launch; graph replays)
// =====================================================================
__global__ void reset_kernel() {
    int i = threadIdx.x;
    if (i == 0) g_ticket = 0;
    for (int j = i; j < NROW; j += blockDim.x) g_rowdone[j] = 0;
}

// =====================================================================
// Prep: fp32 -> fp16 convert (x)
// =====================================================================
__global__ __launch_bounds__(256) void cvt_kernel(
    const float* __restrict__ in, __half* __restrict__ out, int n4)
{
    int i = blockIdx.x * 256 + threadIdx.x;
    if (i >= n4) return;
    float4 v = ((const float4*)in)[i];
    ((__half2*)out)[2*i]   = __floats2half2_rn(v.x, v.y);
    ((__half2*)out)[2*i+1] = __floats2half2_rn(v.z, v.w);
}

// =====================================================================
// Prep (fused): W1^T, W2^T, w2ext extra cols, wdt — one launch
// =====================================================================
__global__ __launch_bounds__(256) void prep_weights_kernel(
    const float* __restrict__ W1, const float* __restrict__ W2,
    const float* __restrict__ w_up, const float* __restrict__ w_down)
{
    __shared__ float tile[32][33];
    int b = blockIdx.x;
    int tx = threadIdx.x & 31, ty = threadIdx.x >> 5;
    if (b < 1024) {
        int c0 = (b & 63) * 32, r0 = (b >> 6) * 32;   // cols of W1 (2048), rows (512)
        #pragma unroll
        for (int i = 0; i < 4; i++)
            tile[ty + 8*i][tx] = W1[(size_t)(r0 + ty + 8*i) * D_HID + c0 + tx];
        __syncthreads();
        #pragma unroll
        for (int i = 0; i < 4; i++)
            g_w1t[(size_t)(c0 + ty + 8*i) * D_IN + r0 + tx] = __float2half_rn(tile[tx][ty + 8*i]);
    } else if (b < 2048) {
        int b2 = b - 1024;
        int c0 = (b2 & 15) * 32, r0 = (b2 >> 4) * 32; // cols of W2 (512), rows (2048)
        #pragma unroll
        for (int i = 0; i < 4; i++)
            tile[ty + 8*i][tx] = W2[(size_t)(r0 + ty + 8*i) * D_IN + c0 + tx];
        __syncthreads();
        #pragma unroll
        for (int i = 0; i < 4; i++)
            g_w2e[(size_t)(c0 + ty + 8*i) * K2 + r0 + tx] = __float2half_rn(tile[tx][ty + 8*i]);
    } else {
        int b3 = b - 2048;
        if (b3 < 64) {
            int i = b3 * 256 + threadIdx.x;          // over 512*32
            int n = i >> 5, c = i & 31;
            float v = 0.0f;
            if (c < N_EXP * R_LORA) v = w_up[(size_t)c * D_IN + n];
            g_w2e[(size_t)n * K2 + D_HID + c] = __float2half_rn(v);
        } else {
            int i = (b3 - 64) * 256 + threadIdx.x;   // over 32*512
            int n = i >> 9, d = i & 511;
            float v = 0.0f;
            if (n < N_EXP * R_LORA) {
                int e = n >> 3, r = n & 7;
                v = w_down[(size_t)e * (D_IN * R_LORA) + (size_t)d * R_LORA + r];
            }
            g_wdt[(size_t)n * D_IN + d] = __float2half_rn(v);
        }
    }
}

// =====================================================================
// Mega-kernel pieces (128-thread CTAs, 3 CTA/SM)
// =====================================================================
#define MAT_BYTES 10240     // 128 * 40 * 2
#define STAGE_BYTES 20480   // A + B
#define GSMEM_BYTES (3 * STAGE_BYTES + 512)

#define LMAT_A 10240
#define LSTAGE 12800

// --- LoRA job: down = x @ wdt^T [128 tok x 32], gated-gelu epilogue ---
// 4 warps, each warp covers 32 tokens (2 m16 tiles) x 32 cols.
__device__ void do_lora(int m, const float* __restrict__ probs,
                        const int* __restrict__ idx, char* sm, int tid)
{
    uint32_t sb = smem_to_u32(sm);
    int lane = tid & 31, w = tid >> 5;
    int mBase = m * 128;
    const int NS = D_IN / 32;   // 16

    float acc[2][4][4];
    #pragma unroll
    for (int i = 0; i < 2; i++)
        #pragma unroll
        for (int j = 0; j < 4; j++)
            #pragma unroll
            for (int q = 0; q < 4; q++) acc[i][j][q] = 0.0f;

    auto issue = [&](int s) {
        uint32_t sbuf = sb + (uint32_t)(s % 3) * LSTAGE;
        int kt = s * 32;
        // A: 128 rows x 4 chunks = 512 chunks over 128 threads (4/thread)
        #pragma unroll
        for (int c = 0; c < 4; ++c) {
            int q = tid + 128 * c;
            int row = q >> 2, ch = q & 3;
            CP_ASYNC16(sbuf + (uint32_t)row * 80 + (uint32_t)ch * 16,
                       g_xh + (size_t)(mBase + row) * D_IN + kt + ch * 8);
        }
        // B: 32 rows x 4 chunks = 128 chunks (1/thread)
        {
            int row = tid >> 2, ch = tid & 3;
            CP_ASYNC16(sbuf + LMAT_A + (uint32_t)row * 80 + (uint32_t)ch * 16,
                       g_wdt + (size_t)row * D_IN + kt + ch * 8);
        }
    };

    issue(0); CP_COMMIT();
    issue(1); CP_COMMIT();

    uint32_t a_off = (uint32_t)(w * 32 + (lane & 15)) * 80 + (uint32_t)((lane >> 4) * 8) * 2;
    uint32_t b_off = LMAT_A + (uint32_t)((lane & 7) + ((lane >> 4) << 3)) * 80
                   + (uint32_t)(((lane >> 3) & 1) * 8) * 2;

    #pragma unroll 1
    for (int s = 0; s < NS; ++s) {
        CP_WAIT1();
        __syncthreads();
        if (s + 2 < NS) issue(s + 2);
        CP_COMMIT();

        uint32_t buf = sb + (uint32_t)(s % 3) * LSTAGE;
        #pragma unroll
        for (int ks = 0; ks < 2; ++ks) {
            uint32_t kb = (uint32_t)ks * 32;
            uint32_t ah[2][4], bh[4][2];
            #pragma unroll
            for (int i = 0; i < 2; ++i)
                LDMATRIX_X4(ah[i][0], ah[i][1], ah[i][2], ah[i][3],
                            buf + a_off + (uint32_t)(i * 16) * 80 + kb);
            #pragma unroll
            for (int jj = 0; jj < 2; ++jj)
                LDMATRIX_X4(bh[2*jj][0], bh[2*jj][1], bh[2*jj+1][0], bh[2*jj+1][1],
                            buf + b_off + (uint32_t)(jj * 16) * 80 + kb);
            #pragma unroll
            for (int i = 0; i < 2; ++i)
                #pragma unroll
                for (int j = 0; j < 4; ++j)
                    MMA_FP16(acc[i][j], ah[i], bh[j][0], bh[j][1]);
        }
    }
    __syncthreads();   // reads done before smem reuse by next job

    int g = lane >> 2, tq = lane & 3;
    #pragma unroll
    for (int i = 0; i < 2; ++i) {
        int t0 = mBase + w * 32 + i * 16 + g;
        int t1 = t0 + 8;
        int e00 = idx[2*t0], e01 = idx[2*t0+1];
        int e10 = idx[2*t1], e11 = idx[2*t1+1];
        float p00 = probs[2*t0], p01 = probs[2*t0+1];
        float p10 = probs[2*t1], p11 = probs[2*t1+1];
        #pragma unroll
        for (int j = 0; j < 3; ++j) {          // j == expert id
            float w0 = (e00 == j) ? p00 : ((e01 == j) ? p01 : 0.0f);
            float w1 = (e10 == j) ? p10 : ((e11 == j) ? p11 : 0.0f);
            float v0 = w0 * gelu_exact(acc[i][j][0]);
            float v1 = w0 * gelu_exact(acc[i][j][1]);
            float v2 = w1 * gelu_exact(acc[i][j][2]);
            float v3 = w1 * gelu_exact(acc[i][j][3]);
            int c = j * 8 + tq * 2;
            *(__half2*)(g_h + (size_t)t0 * K2 + D_HID + c) = __floats2half2_rn(v0, v1);
            *(__half2*)(g_h + (size_t)t1 * K2 + D_HID + c) = __floats2half2_rn(v2, v3);
        }
    }
}

// --- GEMM job: CTA 128x128, 4 warps (warp tile 64x64), 3-buf cp.async ---
template<int KTOT, int LD, bool IS_GEMM1>
__device__ void do_gemm(int mBase, int nBase,
                        const __half* __restrict__ A, const __half* __restrict__ B,
                        const float* __restrict__ bias,
                        __half* __restrict__ OutH, float* __restrict__ OutF,
                        char* sm, int tid)
{
    uint32_t sb = smem_to_u32(sm);
    float* bias_s = (float*)(sm + 3 * STAGE_BYTES);

    int lane = tid & 31, wid = tid >> 5;
    int wm = wid >> 1, wn = wid & 1;          // warp grid 2 x 2

    bias_s[tid] = bias[nBase + tid];

    // loader: 256 rows (128 A + 128 B) x 4 chunks = 1024 chunks, 8/thread
    int r0 = tid >> 2, ch = tid & 3;          // r0 in [0,32), fixed chunk col
    size_t gA = (size_t)(mBase + r0) * LD + ch * 8;
    size_t gB = (size_t)(nBase + r0) * LD + ch * 8;
    uint32_t soA = (uint32_t)r0 * 80 + (uint32_t)ch * 16;

    const int NS = KTOT / 32;

    float acc[4][8][4];
    #pragma unroll
    for (int i = 0; i < 4; i++)
        #pragma unroll
        for (int j = 0; j < 8; j++)
            #pragma unroll
            for (int q = 0; q < 4; q++) acc[i][j][q] = 0.0f;

    auto issue = [&](int s) {
        uint32_t sbuf = sb + (uint32_t)(s % 3) * STAGE_BYTES;
        int kt = s * 32;
        #pragma unroll
        for (int c = 0; c < 4; ++c)
            CP_ASYNC16(sbuf + soA + (uint32_t)(32 * c) * 80,
                       A + gA + (size_t)(32 * c) * LD + kt);
        #pragma unroll
        for (int c = 0; c < 4; ++c)
            CP_ASYNC16(sbuf + MAT_BYTES + soA + (uint32_t)(32 * c) * 80,
                       B + gB + (size_t)(32 * c) * LD + kt);
    };

    issue(0); CP_COMMIT();
    issue(1); CP_COMMIT();

    uint32_t a_off = (uint32_t)(wm * 64 + (lane & 15)) * 80 + (uint32_t)((lane >> 4) * 8) * 2;
    uint32_t b_off = (uint32_t)(wn * 64 + (lane & 7) + ((lane >> 4) << 3)) * 80
                   + (uint32_t)(((lane >> 3) & 1) * 8) * 2;

    #pragma unroll 1
    for (int s = 0; s < NS; ++s) {
        CP_WAIT1();
        __syncthreads();
        if (s + 2 < NS) issue(s + 2);
        CP_COMMIT();

        uint32_t buf = sb + (uint32_t)(s % 3) * STAGE_BYTES;
        #pragma unroll
        for (int ks = 0; ks < 2; ++ks) {
            uint32_t kb = (uint32_t)(ks * 16) * 2;
            uint32_t ah[4][4];
            #pragma unroll
            for (int i = 0; i < 4; ++i)
                LDMATRIX_X4(ah[i][0], ah[i][1], ah[i][2], ah[i][3],
                            buf + a_off + (uint32_t)(i * 16) * 80 + kb);
            // B in two halves of 32 cols to cap live registers
            #pragma unroll
            for (int h = 0; h < 2; ++h) {
                uint32_t bh[4][2];
                #pragma unroll
                for (int jj = 0; jj < 2; ++jj)
                    LDMATRIX_X4(bh[2*jj][0], bh[2*jj][1], bh[2*jj+1][0], bh[2*jj+1][1],
                                buf + MAT_BYTES + b_off
                                + (uint32_t)(h * 32 + jj * 16) * 80 + kb);
                #pragma unroll
                for (int i = 0; i < 4; ++i)
                    #pragma unroll
                    for (int j = 0; j < 4; ++j)
                        MMA_FP16(acc[i][h * 4 + j], ah[i], bh[j][0], bh[j][1]);
            }
        }
    }
    __syncthreads();   // reads done before next job's loads overwrite smem

    int g = lane >> 2, tq = lane & 3;
    #pragma unroll
    for (int i = 0; i < 4; ++i) {
        int row0 = mBase + wm * 64 + i * 16 + g;
        int row1 = row0 + 8;
        #pragma unroll
        for (int j = 0; j < 8; ++j) {
            int nloc = wn * 64 + j * 8 + tq * 2;
            float b0 = bias_s[nloc], b1 = bias_s[nloc + 1];
            float v0 = acc[i][j][0] + b0, v1 = acc[i][j][1] + b1;
            float v2 = acc[i][j][2] + b0, v3 = acc[i][j][3] + b1;
            if (IS_GEMM1) {
                v0 = gelu_exact(v0); v1 = gelu_exact(v1);
                v2 = gelu_exact(v2); v3 = gelu_exact(v3);
                size_t o0 = (size_t)row0 * K2 + nBase + nloc;
                size_t o1 = (size_t)row1 * K2 + nBase + nloc;
                *(__half2*)(OutH + o0) = __floats2half2_rn(v0, v1);
                *(__half2*)(OutH + o1) = __floats2half2_rn(v2, v3);
            } else {
                size_t o0 = (size_t)row0 * D_IN + nBase + nloc;
                size_t o1 = (size_t)row1 * D_IN + nBase + nloc;
                *(float2*)(OutF + o0) = make_float2(v0, v1);
                *(float2*)(OutF + o1) = make_float2(v2, v3);
            }
        }
    }
}

// --- persistent scheduler (identical job map to round 9) ---
__global__ __launch_bounds__(128, 3) void mega_kernel(
    const float* __restrict__ b1, const float* __restrict__ b2,
    const float* __restrict__ probs, const int* __restrict__ idx,
    float* __restrict__ out)
{
    extern __shared__ char sm[];
    __shared__ int s_job;
    int tid = threadIdx.x;

    for (;;) {
        __syncthreads();
        if (tid == 0) s_job = atomicAdd(&g_ticket, 1);
        __syncthreads();
        int job = s_job;
        if (job >= NJOBS) return;

        int type, m, n = 0;
        if (job < 392) { type = 0; m = job; }
        else {
            int j = job - 392;
            if (j < 768) { type = 1; m = j >> 4; n = j & 15; }
            else if (j < 7648) {
                int t = j - 768, b = t / 20, r = t % 20;
                if (r < 16) { type = 1; m = 48 + b; n = r; }
                else        { type = 2; m = b;      n = r - 16; }
            } else {
                int t = j - 7648; type = 2; m = 344 + (t >> 2); n = t & 3;
            }
        }

        if (type == 0) {
            do_lora(m, probs, idx, sm, tid);
            __threadfence();
            __syncthreads();
            if (tid == 0) atomicAdd(&g_rowdone[m], 1);
        } else if (type == 1) {
            do_gemm<D_IN, D_IN, true>(m * 128, n * 128, g_xh, g_w1t, b1,
                                      g_h, nullptr, sm, tid);
            __threadfence();
            __syncthreads();
            if (tid == 0) atomicAdd(&g_rowdone[m], 1);
        } else {
            if (tid == 0) {
                while (atomicAdd(&g_rowdone[m], 0) < 17) __nanosleep(128);
            }
            __syncthreads();
            __threadfence();
            do_gemm<K2, K2, false>(m * 128, n * 128, g_h, g_w2e, b2,
                                   nullptr, out, sm, tid);
        }
    }
}

// =====================================================================
// launch
// =====================================================================
extern "C" void kernel_launch(void* const* d_in, const int* in_sizes, int n_in,
                              void* d_out, int out_size) {
    const float* x          = (const float*)d_in[0];
    const float* W1         = (const float*)d_in[1];
    const float* b1         = (const float*)d_in[2];
    const float* W2         = (const float*)d_in[3];
    const float* b2         = (const float*)d_in[4];
    const float* w_down     = (const float*)d_in[5];
    const float* w_up       = (const float*)d_in[6];
    const float* topk_probs = (const float*)d_in[8];
    const int*   topk_idx   = (const int*)d_in[9];
    float* out = (float*)d_out;
    (void)in_sizes; (void)n_in; (void)out_size;

    __half* xh;
    cudaGetSymbolAddress((void**)&xh, g_xh);

    cudaFuncSetAttribute(mega_kernel,
                         cudaFuncAttributeMaxDynamicSharedMemorySize, GSMEM_BYTES);

    reset_kernel<<<1, 512>>>();

    int n4 = T_TOK * D_IN / 4;
    cvt_kernel<<<n4 / 256, 256>>>(x, xh, n4);
    prep_weights_kernel<<<2176, 256>>>(W1, W2, w_up, w_down);

    mega_kernel<<<444, 128, GSMEM_BYTES>>>(b1, b2, topk_probs, topk_idx, out);
}